// round 1
// baseline (speedup 1.0000x reference)
#include <cuda_runtime.h>
#include <math.h>

#define NQc   40000
#define EDc   256
#define NHc   8
#define HDc   32
#define NBQc  2
#define NPc   4
#define Hc    200
#define Wc    200

// ---------------- scratch (device globals; no allocation allowed) ----------
__device__ float g_value[NBQc * NQc * EDc];   // (2,40000,256)  81.9 MB
__device__ float g_so[NQc * 128];             // (40000,128)
__device__ float g_aw[NQc * 64];              // (40000,64)
__device__ float g_attn[NQc * EDc];           // (40000,256)

// ============================================================================
// GEMM 1: g_value = prev_bev @ Wv + bv     M=80000, K=256, N=256 (all exact)
// 128x128x8 tiles, 256 threads, 8x8 per thread.
// ============================================================================
__global__ __launch_bounds__(256, 2)
void gemm_value_kernel(const float* __restrict__ A,   // prev_bev [80000,256]
                       const float* __restrict__ B,   // Wv [256,256]
                       const float* __restrict__ bias)// bv [256]
{
    __shared__ float As[8][128];
    __shared__ float Bs[8][128];
    const int tid = threadIdx.x;
    const int m0 = blockIdx.x * 128;
    const int n0 = blockIdx.y * 128;
    const int arow = tid >> 1, acol = (tid & 1) * 4;
    const int brow = tid >> 5, bcol = (tid & 31) * 4;
    const int ty = tid >> 4, tx = tid & 15;

    float acc[8][8];
    #pragma unroll
    for (int i = 0; i < 8; i++)
        #pragma unroll
        for (int j = 0; j < 8; j++) acc[i][j] = 0.f;

    for (int k0 = 0; k0 < 256; k0 += 8) {
        float4 av = *(const float4*)&A[(size_t)(m0 + arow) * 256 + k0 + acol];
        float4 bw = *(const float4*)&B[(size_t)(k0 + brow) * 256 + n0 + bcol];
        As[acol + 0][arow] = av.x;
        As[acol + 1][arow] = av.y;
        As[acol + 2][arow] = av.z;
        As[acol + 3][arow] = av.w;
        *(float4*)&Bs[brow][bcol] = bw;
        __syncthreads();
        #pragma unroll
        for (int kk = 0; kk < 8; kk++) {
            float a[8], b[8];
            *(float4*)(a)     = *(const float4*)&As[kk][ty * 8];
            *(float4*)(a + 4) = *(const float4*)&As[kk][ty * 8 + 4];
            *(float4*)(b)     = *(const float4*)&Bs[kk][tx * 8];
            *(float4*)(b + 4) = *(const float4*)&Bs[kk][tx * 8 + 4];
            #pragma unroll
            for (int i = 0; i < 8; i++)
                #pragma unroll
                for (int j = 0; j < 8; j++)
                    acc[i][j] = fmaf(a[i], b[j], acc[i][j]);
        }
        __syncthreads();
    }

    float bb[8];
    #pragma unroll
    for (int j = 0; j < 8; j++) bb[j] = bias[n0 + tx * 8 + j];
    #pragma unroll
    for (int i = 0; i < 8; i++) {
        float4 v0 = make_float4(acc[i][0] + bb[0], acc[i][1] + bb[1],
                                acc[i][2] + bb[2], acc[i][3] + bb[3]);
        float4 v1 = make_float4(acc[i][4] + bb[4], acc[i][5] + bb[5],
                                acc[i][6] + bb[6], acc[i][7] + bb[7]);
        size_t row = (size_t)(m0 + ty * 8 + i);
        *(float4*)&g_value[row * 256 + n0 + tx * 8]     = v0;
        *(float4*)&g_value[row * 256 + n0 + tx * 8 + 4] = v1;
    }
}

// ============================================================================
// GEMM 2: [so | aw] = concat(prev_bev[:1], query) @ [Wso | Waw] + [bso | baw]
//   M=40000, K=512, N=192. M and N need guards.
// ============================================================================
__global__ __launch_bounds__(256, 2)
void gemm_soaw_kernel(const float* __restrict__ prev_bev, // [80000,256] (use rows <40000)
                      const float* __restrict__ query,    // [40000,256]
                      const float* __restrict__ Wso,      // [512,128]
                      const float* __restrict__ bso,      // [128]
                      const float* __restrict__ Waw,      // [512,64]
                      const float* __restrict__ baw)      // [64]
{
    __shared__ float As[8][128];
    __shared__ float Bs[8][128];
    const int tid = threadIdx.x;
    const int m0 = blockIdx.x * 128;
    const int n0 = blockIdx.y * 128;
    const int arow = tid >> 1, acol = (tid & 1) * 4;
    const int brow = tid >> 5, bcol = (tid & 31) * 4;
    const int ty = tid >> 4, tx = tid & 15;

    float acc[8][8];
    #pragma unroll
    for (int i = 0; i < 8; i++)
        #pragma unroll
        for (int j = 0; j < 8; j++) acc[i][j] = 0.f;

    int m = m0 + arow; if (m >= NQc) m = NQc - 1;   // clamp load row (store guarded)

    for (int k0 = 0; k0 < 512; k0 += 8) {
        int k = k0 + acol;
        float4 av;
        if (k < 256) av = *(const float4*)&prev_bev[(size_t)m * 256 + k];
        else         av = *(const float4*)&query[(size_t)m * 256 + (k - 256)];

        int kr = k0 + brow;
        int col = n0 + bcol;
        float4 bw;
        if (col < 128)       bw = *(const float4*)&Wso[(size_t)kr * 128 + col];
        else if (col < 192)  bw = *(const float4*)&Waw[(size_t)kr * 64 + (col - 128)];
        else                 bw = make_float4(0.f, 0.f, 0.f, 0.f);

        As[acol + 0][arow] = av.x;
        As[acol + 1][arow] = av.y;
        As[acol + 2][arow] = av.z;
        As[acol + 3][arow] = av.w;
        *(float4*)&Bs[brow][bcol] = bw;
        __syncthreads();
        #pragma unroll
        for (int kk = 0; kk < 8; kk++) {
            float a[8], b[8];
            *(float4*)(a)     = *(const float4*)&As[kk][ty * 8];
            *(float4*)(a + 4) = *(const float4*)&As[kk][ty * 8 + 4];
            *(float4*)(b)     = *(const float4*)&Bs[kk][tx * 8];
            *(float4*)(b + 4) = *(const float4*)&Bs[kk][tx * 8 + 4];
            #pragma unroll
            for (int i = 0; i < 8; i++)
                #pragma unroll
                for (int j = 0; j < 8; j++)
                    acc[i][j] = fmaf(a[i], b[j], acc[i][j]);
        }
        __syncthreads();
    }

    #pragma unroll
    for (int i = 0; i < 8; i++) {
        int row = m0 + ty * 8 + i;
        if (row >= NQc) continue;
        #pragma unroll
        for (int j = 0; j < 8; j++) {
            int col = n0 + tx * 8 + j;
            if (col < 128)
                g_so[(size_t)row * 128 + col] = acc[i][j] + bso[col];
            else if (col < 192)
                g_aw[(size_t)row * 64 + (col - 128)] = acc[i][j] + baw[col - 128];
        }
    }
}

// ============================================================================
// Softmax + bilinear deformable sampling.
// One warp per (q, h); lane = hd channel. Accumulates over bq and p.
// ============================================================================
__global__ __launch_bounds__(256)
void sample_kernel(const float* __restrict__ ref2d) // [2,40000,1,2]
{
    const int wq = blockIdx.x * 8 + (threadIdx.x >> 5);
    if (wq >= NQc * NHc) return;
    const int q = wq >> 3;
    const int h = wq & 7;
    const int lane = threadIdx.x & 31;

    const float* so_q = &g_so[(size_t)q * 128];
    const float* aw_q = &g_aw[(size_t)q * 64];

    float acc = 0.f;
    #pragma unroll
    for (int b = 0; b < NBQc; b++) {
        // softmax over the 4 points of this (q,h,b)
        const int awbase = (h * 2 + b) * 4;
        float a0 = aw_q[awbase + 0], a1 = aw_q[awbase + 1];
        float a2 = aw_q[awbase + 2], a3 = aw_q[awbase + 3];
        float mx = fmaxf(fmaxf(a0, a1), fmaxf(a2, a3));
        float e0 = __expf(a0 - mx), e1 = __expf(a1 - mx);
        float e2 = __expf(a2 - mx), e3 = __expf(a3 - mx);
        float inv = 1.f / (e0 + e1 + e2 + e3);
        float wts[4] = {e0 * inv, e1 * inv, e2 * inv, e3 * inv};

        const float rx = ref2d[((size_t)b * NQc + q) * 2 + 0];
        const float ry = ref2d[((size_t)b * NQc + q) * 2 + 1];

        const float* vbase = &g_value[(size_t)b * NQc * EDc + h * 32 + lane];

        #pragma unroll
        for (int p = 0; p < NPc; p++) {
            const int j = ((h * 2 + b) * 4 + p) * 2;
            float lx = rx + so_q[j + 0] * (1.0f / (float)Wc);
            float ly = ry + so_q[j + 1] * (1.0f / (float)Hc);
            float x = lx * (float)Wc - 0.5f;
            float y = ly * (float)Hc - 0.5f;
            float x0f = floorf(x), y0f = floorf(y);
            float wx = x - x0f, wy = y - y0f;
            int ix0 = (int)x0f, iy0 = (int)y0f;

            float v00 = 0.f, v10 = 0.f, v01 = 0.f, v11 = 0.f;
            bool xin0 = (unsigned)ix0 < (unsigned)Wc;
            bool xin1 = (unsigned)(ix0 + 1) < (unsigned)Wc;
            bool yin0 = (unsigned)iy0 < (unsigned)Hc;
            bool yin1 = (unsigned)(iy0 + 1) < (unsigned)Hc;
            if (yin0) {
                size_t r = (size_t)(iy0 * Wc) * EDc;
                if (xin0) v00 = vbase[r + (size_t)ix0 * EDc];
                if (xin1) v10 = vbase[r + (size_t)(ix0 + 1) * EDc];
            }
            if (yin1) {
                size_t r = (size_t)((iy0 + 1) * Wc) * EDc;
                if (xin0) v01 = vbase[r + (size_t)ix0 * EDc];
                if (xin1) v11 = vbase[r + (size_t)(ix0 + 1) * EDc];
            }
            float s = v00 * (1.f - wx) * (1.f - wy)
                    + v10 * wx * (1.f - wy)
                    + v01 * (1.f - wx) * wy
                    + v11 * wx * wy;
            acc = fmaf(wts[p], s, acc);
        }
    }
    g_attn[(size_t)q * EDc + h * 32 + lane] = 0.5f * acc;   // mean over nbq=2
}

// ============================================================================
// GEMM 3: out = g_attn @ Wo + bo + query   M=40000, K=256, N=256 (M guarded)
// ============================================================================
__global__ __launch_bounds__(256, 2)
void gemm_out_kernel(const float* __restrict__ query, // [40000,256]
                     const float* __restrict__ B,     // Wo [256,256]
                     const float* __restrict__ bias,  // bo [256]
                     float* __restrict__ out)         // [40000,256]
{
    __shared__ float As[8][128];
    __shared__ float Bs[8][128];
    const int tid = threadIdx.x;
    const int m0 = blockIdx.x * 128;
    const int n0 = blockIdx.y * 128;
    const int arow = tid >> 1, acol = (tid & 1) * 4;
    const int brow = tid >> 5, bcol = (tid & 31) * 4;
    const int ty = tid >> 4, tx = tid & 15;

    float acc[8][8];
    #pragma unroll
    for (int i = 0; i < 8; i++)
        #pragma unroll
        for (int j = 0; j < 8; j++) acc[i][j] = 0.f;

    int m = m0 + arow; if (m >= NQc) m = NQc - 1;

    for (int k0 = 0; k0 < 256; k0 += 8) {
        float4 av = *(const float4*)&g_attn[(size_t)m * 256 + k0 + acol];
        float4 bw = *(const float4*)&B[(size_t)(k0 + brow) * 256 + n0 + bcol];
        As[acol + 0][arow] = av.x;
        As[acol + 1][arow] = av.y;
        As[acol + 2][arow] = av.z;
        As[acol + 3][arow] = av.w;
        *(float4*)&Bs[brow][bcol] = bw;
        __syncthreads();
        #pragma unroll
        for (int kk = 0; kk < 8; kk++) {
            float a[8], b[8];
            *(float4*)(a)     = *(const float4*)&As[kk][ty * 8];
            *(float4*)(a + 4) = *(const float4*)&As[kk][ty * 8 + 4];
            *(float4*)(b)     = *(const float4*)&Bs[kk][tx * 8];
            *(float4*)(b + 4) = *(const float4*)&Bs[kk][tx * 8 + 4];
            #pragma unroll
            for (int i = 0; i < 8; i++)
                #pragma unroll
                for (int j = 0; j < 8; j++)
                    acc[i][j] = fmaf(a[i], b[j], acc[i][j]);
        }
        __syncthreads();
    }

    float bb[8];
    #pragma unroll
    for (int j = 0; j < 8; j++) bb[j] = bias[n0 + tx * 8 + j];
    #pragma unroll
    for (int i = 0; i < 8; i++) {
        int row = m0 + ty * 8 + i;
        if (row >= NQc) continue;
        const float4 q0 = *(const float4*)&query[(size_t)row * 256 + n0 + tx * 8];
        const float4 q1 = *(const float4*)&query[(size_t)row * 256 + n0 + tx * 8 + 4];
        float4 v0 = make_float4(acc[i][0] + bb[0] + q0.x, acc[i][1] + bb[1] + q0.y,
                                acc[i][2] + bb[2] + q0.z, acc[i][3] + bb[3] + q0.w);
        float4 v1 = make_float4(acc[i][4] + bb[4] + q1.x, acc[i][5] + bb[5] + q1.y,
                                acc[i][6] + bb[6] + q1.z, acc[i][7] + bb[7] + q1.w);
        *(float4*)&out[(size_t)row * 256 + n0 + tx * 8]     = v0;
        *(float4*)&out[(size_t)row * 256 + n0 + tx * 8 + 4] = v1;
    }
}

// ============================================================================
extern "C" void kernel_launch(void* const* d_in, const int* in_sizes, int n_in,
                              void* d_out, int out_size)
{
    const float* query    = (const float*)d_in[0];
    const float* prev_bev = (const float*)d_in[1];
    // d_in[2] = bev_pos (unused by reference)
    const float* ref2d    = (const float*)d_in[3];
    const float* Wv       = (const float*)d_in[4];
    const float* bv       = (const float*)d_in[5];
    const float* Wso      = (const float*)d_in[6];
    const float* bso      = (const float*)d_in[7];
    const float* Waw      = (const float*)d_in[8];
    const float* baw      = (const float*)d_in[9];
    const float* Wo       = (const float*)d_in[10];
    const float* bo       = (const float*)d_in[11];
    float* out = (float*)d_out;

    // 1) value projection: 80000x256x256
    gemm_value_kernel<<<dim3(625, 2), 256>>>(prev_bev, Wv, bv);

    // 2) sampling offsets + attention logits: 40000x512x192
    gemm_soaw_kernel<<<dim3(313, 2), 256>>>(prev_bev, query, Wso, bso, Waw, baw);

    // 3) softmax + bilinear deformable sampling -> g_attn
    sample_kernel<<<NQc * NHc / 8, 256>>>(ref2d);

    // 4) output projection + residual: 40000x256x256
    gemm_out_kernel<<<dim3(313, 2), 256>>>(query, Wo, bo, out);
}

// round 4
// speedup vs baseline: 1.8189x; 1.8189x over previous
#include <cuda_runtime.h>
#include <cuda_bf16.h>
#include <cstdint>
#include <math.h>

#define NQc   40000
#define EDc   256
#define NHc   8
#define NBQc  2
#define NPc   4
#define Hc    200
#define Wc    200

// ---------------- scratch (device globals; no allocation allowed) ----------
__device__ float g_value[NBQc * NQc * EDc];   // (2,40000,256)
__device__ float g_so[NQc * 128];
__device__ float g_aw[NQc * 64];
__device__ float g_attn[NQc * EDc];

// pre-transposed, bf16-split weights: [N][K] row-major
__device__ __nv_bfloat16 g_WvT_hi[256 * 256], g_WvT_lo[256 * 256];
__device__ __nv_bfloat16 g_WoT_hi[256 * 256], g_WoT_lo[256 * 256];
__device__ __nv_bfloat16 g_W2T_hi[256 * 512], g_W2T_lo[256 * 512]; // n<128: Wso, 128..191: Waw, >=192: 0
__device__ float g_bias2[256];

// ============================ helpers ======================================
__device__ __forceinline__ uint32_t smem_u32(const void* p) {
    uint32_t a;
    asm("{ .reg .u64 t; cvta.to.shared.u64 t, %1; cvt.u32.u64 %0, t; }" : "=r"(a) : "l"(p));
    return a;
}
__device__ __forceinline__ float bf_round(float x) {
    return __bfloat162float(__float2bfloat16(x));
}
__device__ __forceinline__ uint32_t pack_bf16x2(float hi, float lo) {
    uint32_t r;
    asm("cvt.rn.bf16x2.f32 %0, %1, %2;" : "=r"(r) : "f"(hi), "f"(lo));
    return r;
}
__device__ __forceinline__ void ldsm4(uint32_t* r, uint32_t addr) {
    asm volatile("ldmatrix.sync.aligned.m8n8.x4.shared.b16 {%0,%1,%2,%3}, [%4];"
                 : "=r"(r[0]), "=r"(r[1]), "=r"(r[2]), "=r"(r[3]) : "r"(addr));
}
__device__ __forceinline__ void mma16816(float* c, const uint32_t* a, uint32_t b0, uint32_t b1) {
    asm volatile("mma.sync.aligned.m16n8k16.row.col.f32.bf16.bf16.f32 "
                 "{%0,%1,%2,%3}, {%4,%5,%6,%7}, {%8,%9}, {%0,%1,%2,%3};"
                 : "+f"(c[0]), "+f"(c[1]), "+f"(c[2]), "+f"(c[3])
                 : "r"(a[0]), "r"(a[1]), "r"(a[2]), "r"(a[3]), "r"(b0), "r"(b1));
}
#define CP16(smaddr, gptr) \
    asm volatile("cp.async.cg.shared.global [%0], [%1], 16;" :: "r"(smaddr), "l"(gptr))
#define CP_COMMIT() asm volatile("cp.async.commit_group;" ::: "memory")
#define CP_WAIT0()  asm volatile("cp.async.wait_group 0;" ::: "memory")

// ============================ weight prep ==================================
__global__ void prep_weights(const float* __restrict__ Wv, const float* __restrict__ Wso,
                             const float* __restrict__ Waw, const float* __restrict__ Wo,
                             const float* __restrict__ bso, const float* __restrict__ baw)
{
    int idx = blockIdx.x * 256 + threadIdx.x;
    if (idx < 256 * 256) {
        int n = idx >> 8, k = idx & 255;
        float v = Wv[k * 256 + n];
        float h = bf_round(v);
        g_WvT_hi[n * 256 + k] = __float2bfloat16(h);
        g_WvT_lo[n * 256 + k] = __float2bfloat16(v - h);
        float o = Wo[k * 256 + n];
        float ho = bf_round(o);
        g_WoT_hi[n * 256 + k] = __float2bfloat16(ho);
        g_WoT_lo[n * 256 + k] = __float2bfloat16(o - ho);
    }
    if (idx < 256 * 512) {
        int n = idx >> 9, k = idx & 511;
        float v = 0.f;
        if (n < 128)      v = Wso[k * 128 + n];
        else if (n < 192) v = Waw[k * 64 + (n - 128)];
        float h = bf_round(v);
        g_W2T_hi[n * 512 + k] = __float2bfloat16(h);
        g_W2T_lo[n * 512 + k] = __float2bfloat16(v - h);
    }
    if (idx < 256) {
        float b = 0.f;
        if (idx < 128)      b = bso[idx];
        else if (idx < 192) b = baw[idx - 128];
        g_bias2[idx] = b;
    }
}

// ============================ mma.sync GEMM ================================
// D = A(fp32, split to bf16 hi/lo) @ B^T(pre-split bf16).
// Block tile 128x128, 8 warps (4x2), warp tile 32x64, k-chunk 32, 2-stage.
// smem row = 32 bf16 + 8 pad = 80 bytes (bank-conflict-free ldmatrix).
#define ROWB   80
#define T_AHI  0
#define T_ALO  10240
#define T_BHI  20480
#define T_BLO  30720
#define STAGEB 40960
#define SMEM_DYN_BYTES (2 * STAGEB)

template <int MODE>
__global__ __launch_bounds__(256, 1)
void tsa_gemm(const float* __restrict__ A, const float* __restrict__ Aq,
              const float* __restrict__ bias, const float* __restrict__ resid,
              float* __restrict__ outp)
{
    constexpr int KT   = (MODE == 1) ? 512 : 256;
    constexpr int MTOT = (MODE == 0) ? 80000 : 40000;
    constexpr int NC   = KT / 32;

    extern __shared__ char sm[];
    const uint32_t smb = smem_u32(sm);

    const int tid  = threadIdx.x;
    const int lane = tid & 31;
    const int wid  = tid >> 5;
    const int wm   = wid >> 1;       // 0..3
    const int wn   = wid & 1;        // 0..1
    const int m0   = blockIdx.x * 128;
    const int n0   = blockIdx.y * 128;

    const float* Abase = (MODE == 2) ? g_attn : A;
    const __nv_bfloat16* BTh = (MODE == 0) ? g_WvT_hi : (MODE == 1) ? g_W2T_hi : g_WoT_hi;
    const __nv_bfloat16* BTl = (MODE == 0) ? g_WvT_lo : (MODE == 1) ? g_W2T_lo : g_WoT_lo;

    // A load/store mapping: thread t -> row t>>1, k-half (t&1)*16
    const int arow = tid >> 1;
    const int akh  = (tid & 1) * 16;
    int agrow = m0 + arow; if (agrow > MTOT - 1) agrow = MTOT - 1;

    // B cp.async mapping: thread t -> row t>>1, segs (t&1)*2 + {0,1}
    const int brow  = tid >> 1;
    const int bseg0 = (tid & 1) * 2;
    const int bn    = n0 + brow;     // < 256 always

    // ldmatrix per-thread offsets
    const int grp = lane >> 3, r = lane & 7;
    const uint32_t a_off = (uint32_t)((wm * 32 + ((grp & 1) << 3) + r) * ROWB + (grp >> 1) * 16);
    const uint32_t b_off = (uint32_t)((wn * 64 + ((grp >> 1) << 3) + r) * ROWB + (grp & 1) * 16);

    float acc[2][8][4];
    #pragma unroll
    for (int mt = 0; mt < 2; mt++)
        #pragma unroll
        for (int nt = 0; nt < 8; nt++)
            #pragma unroll
            for (int i = 0; i < 4; i++) acc[mt][nt][i] = 0.f;

    float av[16];

    // ---- prologue: load chunk 0 into stage 0 ----
    {
        const float* src = Abase; int kl = 0;
        const float4* p = (const float4*)(src + (size_t)agrow * 256 + kl + akh);
        #pragma unroll
        for (int j = 0; j < 4; j++) {
            float4 v = p[j];
            av[j*4+0] = v.x; av[j*4+1] = v.y; av[j*4+2] = v.z; av[j*4+3] = v.w;
        }
        const __nv_bfloat16* gh = BTh + (size_t)bn * KT + bseg0 * 8;
        const __nv_bfloat16* gl = BTl + (size_t)bn * KT + bseg0 * 8;
        uint32_t sh = smb + T_BHI + brow * ROWB + bseg0 * 16;
        uint32_t sl = sh + (T_BLO - T_BHI);
        CP16(sh, gh); CP16(sh + 16, gh + 8);
        CP16(sl, gl); CP16(sl + 16, gl + 8);
        CP_COMMIT();

        uint32_t hp[8], lp[8];
        #pragma unroll
        for (int j = 0; j < 8; j++) {
            float x0 = av[2*j], x1 = av[2*j+1];
            float h0 = bf_round(x0), h1 = bf_round(x1);
            hp[j] = pack_bf16x2(h1, h0);
            lp[j] = pack_bf16x2(x1 - h1, x0 - h0);
        }
        char* dst = sm + arow * ROWB + akh * 2;
        *(uint4*)(dst + T_AHI)      = ((uint4*)hp)[0];
        *(uint4*)(dst + T_AHI + 16) = ((uint4*)hp)[1];
        *(uint4*)(dst + T_ALO)      = ((uint4*)lp)[0];
        *(uint4*)(dst + T_ALO + 16) = ((uint4*)lp)[1];
        CP_WAIT0();
        __syncthreads();
    }

    for (int c = 0; c < NC; c++) {
        const int stg  = c & 1;
        const int nstg = stg ^ 1;
        const bool more = (c + 1 < NC);

        // prefetch chunk c+1
        if (more) {
            int k0 = (c + 1) * 32;
            const float* src = Abase; int kl = k0;
            if (MODE == 1 && kl >= 256) { src = Aq; kl -= 256; }
            const float4* p = (const float4*)(src + (size_t)agrow * 256 + kl + akh);
            #pragma unroll
            for (int j = 0; j < 4; j++) {
                float4 v = p[j];
                av[j*4+0] = v.x; av[j*4+1] = v.y; av[j*4+2] = v.z; av[j*4+3] = v.w;
            }
            const __nv_bfloat16* gh = BTh + (size_t)bn * KT + k0 + bseg0 * 8;
            const __nv_bfloat16* gl = BTl + (size_t)bn * KT + k0 + bseg0 * 8;
            uint32_t sh = smb + nstg * STAGEB + T_BHI + brow * ROWB + bseg0 * 16;
            uint32_t sl = sh + (T_BLO - T_BHI);
            CP16(sh, gh); CP16(sh + 16, gh + 8);
            CP16(sl, gl); CP16(sl + 16, gl + 8);
            CP_COMMIT();
        }

        // compute chunk c
        const uint32_t base = smb + stg * STAGEB;
        #pragma unroll
        for (int ks = 0; ks < 32; ks += 16) {
            uint32_t ah[2][4], al[2][4];
            #pragma unroll
            for (int mt = 0; mt < 2; mt++) {
                ldsm4(ah[mt], base + T_AHI + a_off + mt * (16 * ROWB) + ks * 2);
                ldsm4(al[mt], base + T_ALO + a_off + mt * (16 * ROWB) + ks * 2);
            }
            uint32_t bh[4][4], bl[4][4];
            #pragma unroll
            for (int pr = 0; pr < 4; pr++) {
                ldsm4(bh[pr], base + T_BHI + b_off + pr * (16 * ROWB) + ks * 2);
                ldsm4(bl[pr], base + T_BLO + b_off + pr * (16 * ROWB) + ks * 2);
            }
            #pragma unroll
            for (int mt = 0; mt < 2; mt++)
                #pragma unroll
                for (int nt = 0; nt < 8; nt++) {
                    uint32_t bh0 = bh[nt >> 1][(nt & 1) * 2], bh1 = bh[nt >> 1][(nt & 1) * 2 + 1];
                    uint32_t bl0 = bl[nt >> 1][(nt & 1) * 2], bl1 = bl[nt >> 1][(nt & 1) * 2 + 1];
                    mma16816(acc[mt][nt], ah[mt], bh0, bh1);
                    mma16816(acc[mt][nt], ah[mt], bl0, bl1);
                    mma16816(acc[mt][nt], al[mt], bh0, bh1);
                }
        }

        // stage A(c+1), drain cp.async, flip
        if (more) {
            uint32_t hp[8], lp[8];
            #pragma unroll
            for (int j = 0; j < 8; j++) {
                float x0 = av[2*j], x1 = av[2*j+1];
                float h0 = bf_round(x0), h1 = bf_round(x1);
                hp[j] = pack_bf16x2(h1, h0);
                lp[j] = pack_bf16x2(x1 - h1, x0 - h0);
            }
            char* dst = sm + nstg * STAGEB + arow * ROWB + akh * 2;
            *(uint4*)(dst + T_AHI)      = ((uint4*)hp)[0];
            *(uint4*)(dst + T_AHI + 16) = ((uint4*)hp)[1];
            *(uint4*)(dst + T_ALO)      = ((uint4*)lp)[0];
            *(uint4*)(dst + T_ALO + 16) = ((uint4*)lp)[1];
            CP_WAIT0();
            __syncthreads();
        }
    }

    // ---- epilogue: direct float2 stores ----
    #pragma unroll
    for (int mt = 0; mt < 2; mt++) {
        const int rbase = m0 + wm * 32 + mt * 16 + (lane >> 2);
        #pragma unroll
        for (int nt = 0; nt < 8; nt++) {
            const int gn = n0 + wn * 64 + nt * 8 + (lane & 3) * 2;
            #pragma unroll
            for (int hf = 0; hf < 2; hf++) {
                const int row = rbase + hf * 8;
                if (row >= MTOT) continue;
                float c0 = acc[mt][nt][hf * 2], c1 = acc[mt][nt][hf * 2 + 1];
                if (MODE == 0) {
                    float2 o = make_float2(c0 + bias[gn], c1 + bias[gn + 1]);
                    *(float2*)&g_value[(size_t)row * 256 + gn] = o;
                } else if (MODE == 1) {
                    if (gn >= 192) continue;
                    float2 o = make_float2(c0 + g_bias2[gn], c1 + g_bias2[gn + 1]);
                    if (gn < 128) *(float2*)&g_so[(size_t)row * 128 + gn] = o;
                    else          *(float2*)&g_aw[(size_t)row * 64 + (gn - 128)] = o;
                } else {
                    float2 q = *(const float2*)&resid[(size_t)row * 256 + gn];
                    float2 o = make_float2(c0 + bias[gn] + q.x, c1 + bias[gn + 1] + q.y);
                    *(float2*)&outp[(size_t)row * 256 + gn] = o;
                }
            }
        }
    }
}

// ============================ sampling =====================================
__global__ __launch_bounds__(256)
void sample_kernel(const float* __restrict__ ref2d)
{
    const int wq = blockIdx.x * 8 + (threadIdx.x >> 5);
    if (wq >= NQc * NHc) return;
    const int q = wq >> 3;
    const int h = wq & 7;
    const int lane = threadIdx.x & 31;

    const float* so_q = &g_so[(size_t)q * 128];
    const float* aw_q = &g_aw[(size_t)q * 64];

    float acc = 0.f;
    #pragma unroll
    for (int b = 0; b < NBQc; b++) {
        const int awbase = (h * 2 + b) * 4;
        float a0 = aw_q[awbase + 0], a1 = aw_q[awbase + 1];
        float a2 = aw_q[awbase + 2], a3 = aw_q[awbase + 3];
        float mx = fmaxf(fmaxf(a0, a1), fmaxf(a2, a3));
        float e0 = __expf(a0 - mx), e1 = __expf(a1 - mx);
        float e2 = __expf(a2 - mx), e3 = __expf(a3 - mx);
        float inv = 1.f / (e0 + e1 + e2 + e3);
        float wts[4] = {e0 * inv, e1 * inv, e2 * inv, e3 * inv};

        const float rx = ref2d[((size_t)b * NQc + q) * 2 + 0];
        const float ry = ref2d[((size_t)b * NQc + q) * 2 + 1];
        const float* vbase = &g_value[(size_t)b * NQc * EDc + h * 32 + lane];

        #pragma unroll
        for (int p = 0; p < NPc; p++) {
            const int j = ((h * 2 + b) * 4 + p) * 2;
            float x = (rx + so_q[j + 0] * (1.0f / (float)Wc)) * (float)Wc - 0.5f;
            float y = (ry + so_q[j + 1] * (1.0f / (float)Hc)) * (float)Hc - 0.5f;
            float x0f = floorf(x), y0f = floorf(y);
            float wx = x - x0f, wy = y - y0f;
            int ix0 = (int)x0f, iy0 = (int)y0f;

            float v00 = 0.f, v10 = 0.f, v01 = 0.f, v11 = 0.f;
            bool xin0 = (unsigned)ix0 < (unsigned)Wc;
            bool xin1 = (unsigned)(ix0 + 1) < (unsigned)Wc;
            bool yin0 = (unsigned)iy0 < (unsigned)Hc;
            bool yin1 = (unsigned)(iy0 + 1) < (unsigned)Hc;
            if (yin0) {
                size_t rr = (size_t)(iy0 * Wc) * EDc;
                if (xin0) v00 = vbase[rr + (size_t)ix0 * EDc];
                if (xin1) v10 = vbase[rr + (size_t)(ix0 + 1) * EDc];
            }
            if (yin1) {
                size_t rr = (size_t)((iy0 + 1) * Wc) * EDc;
                if (xin0) v01 = vbase[rr + (size_t)ix0 * EDc];
                if (xin1) v11 = vbase[rr + (size_t)(ix0 + 1) * EDc];
            }
            float s = v00 * (1.f - wx) * (1.f - wy)
                    + v10 * wx * (1.f - wy)
                    + v01 * (1.f - wx) * wy
                    + v11 * wx * wy;
            acc = fmaf(wts[p], s, acc);
        }
    }
    g_attn[(size_t)q * EDc + h * 32 + lane] = 0.5f * acc;
}

// ============================================================================
extern "C" void kernel_launch(void* const* d_in, const int* in_sizes, int n_in,
                              void* d_out, int out_size)
{
    const float* query    = (const float*)d_in[0];
    const float* prev_bev = (const float*)d_in[1];
    const float* ref2d    = (const float*)d_in[3];
    const float* Wv       = (const float*)d_in[4];
    const float* bv       = (const float*)d_in[5];
    const float* Wso      = (const float*)d_in[6];
    const float* bso      = (const float*)d_in[7];
    const float* Waw      = (const float*)d_in[8];
    const float* baw      = (const float*)d_in[9];
    const float* Wo       = (const float*)d_in[10];
    const float* bo       = (const float*)d_in[11];
    float* out = (float*)d_out;

    cudaFuncSetAttribute(tsa_gemm<0>, cudaFuncAttributeMaxDynamicSharedMemorySize, SMEM_DYN_BYTES);
    cudaFuncSetAttribute(tsa_gemm<1>, cudaFuncAttributeMaxDynamicSharedMemorySize, SMEM_DYN_BYTES);
    cudaFuncSetAttribute(tsa_gemm<2>, cudaFuncAttributeMaxDynamicSharedMemorySize, SMEM_DYN_BYTES);

    prep_weights<<<512, 256>>>(Wv, Wso, Waw, Wo, bso, baw);

    // 1) value projection: 80000 x 256 x 256
    tsa_gemm<0><<<dim3(625, 2), 256, SMEM_DYN_BYTES>>>(prev_bev, nullptr, bv, nullptr, nullptr);

    // 2) offsets + logits: 40000 x 512 x 192
    tsa_gemm<1><<<dim3(313, 2), 256, SMEM_DYN_BYTES>>>(prev_bev, query, nullptr, nullptr, nullptr);

    // 3) softmax + bilinear sampling
    sample_kernel<<<NQc * NHc / 8, 256>>>(ref2d);

    // 4) output projection + residual: 40000 x 256 x 256
    tsa_gemm<2><<<dim3(313, 2), 256, SMEM_DYN_BYTES>>>(nullptr, nullptr, bo, query, out);
}

// round 5
// speedup vs baseline: 2.2732x; 1.2498x over previous
#include <cuda_runtime.h>
#include <cuda_bf16.h>
#include <cstdint>
#include <math.h>

#define NQc   40000
#define EDc   256
#define NHc   8
#define NBQc  2
#define NPc   4
#define Hc    200
#define Wc    200

// ---------------- scratch (device globals; no allocation allowed) ----------
__device__ float g_value[NBQc * NQc * EDc];   // (2,40000,256)
__device__ float g_so[NQc * 128];
__device__ float g_aw[NQc * 64];
__device__ float g_attn[NQc * EDc];

// pre-transposed, bf16-split weights: [N][K] row-major
__device__ __nv_bfloat16 g_WvT_hi[256 * 256], g_WvT_lo[256 * 256];
__device__ __nv_bfloat16 g_WoT_hi[256 * 256], g_WoT_lo[256 * 256];
__device__ __nv_bfloat16 g_W2T_hi[256 * 512], g_W2T_lo[256 * 512]; // n<128: Wso, 128..191: Waw, >=192: 0
__device__ float g_bias2[256];

// ============================ helpers ======================================
__device__ __forceinline__ uint32_t smem_u32(const void* p) {
    uint32_t a;
    asm("{ .reg .u64 t; cvta.to.shared.u64 t, %1; cvt.u32.u64 %0, t; }" : "=r"(a) : "l"(p));
    return a;
}
__device__ __forceinline__ float bf_round(float x) {
    return __bfloat162float(__float2bfloat16(x));
}
__device__ __forceinline__ uint32_t pack_bf16x2(float hi, float lo) {
    uint32_t r;
    asm("cvt.rn.bf16x2.f32 %0, %1, %2;" : "=r"(r) : "f"(hi), "f"(lo));
    return r;
}
__device__ __forceinline__ void ldsm4(uint32_t* r, uint32_t addr) {
    asm volatile("ldmatrix.sync.aligned.m8n8.x4.shared.b16 {%0,%1,%2,%3}, [%4];"
                 : "=r"(r[0]), "=r"(r[1]), "=r"(r[2]), "=r"(r[3]) : "r"(addr));
}
__device__ __forceinline__ void mma16816(float* c, const uint32_t* a, uint32_t b0, uint32_t b1) {
    asm volatile("mma.sync.aligned.m16n8k16.row.col.f32.bf16.bf16.f32 "
                 "{%0,%1,%2,%3}, {%4,%5,%6,%7}, {%8,%9}, {%0,%1,%2,%3};"
                 : "+f"(c[0]), "+f"(c[1]), "+f"(c[2]), "+f"(c[3])
                 : "r"(a[0]), "r"(a[1]), "r"(a[2]), "r"(a[3]), "r"(b0), "r"(b1));
}
#define CP16(smaddr, gptr) \
    asm volatile("cp.async.cg.shared.global [%0], [%1], 16;" :: "r"(smaddr), "l"(gptr))
#define CP_COMMIT() asm volatile("cp.async.commit_group;" ::: "memory")
#define CP_WAIT0()  asm volatile("cp.async.wait_group 0;" ::: "memory")

// ============================ weight prep ==================================
__global__ void prep_weights(const float* __restrict__ Wv, const float* __restrict__ Wso,
                             const float* __restrict__ Waw, const float* __restrict__ Wo,
                             const float* __restrict__ bso, const float* __restrict__ baw)
{
    int idx = blockIdx.x * 256 + threadIdx.x;
    if (idx < 256 * 256) {
        int n = idx >> 8, k = idx & 255;
        float v = Wv[k * 256 + n];
        float h = bf_round(v);
        g_WvT_hi[n * 256 + k] = __float2bfloat16(h);
        g_WvT_lo[n * 256 + k] = __float2bfloat16(v - h);
        float o = Wo[k * 256 + n];
        float ho = bf_round(o);
        g_WoT_hi[n * 256 + k] = __float2bfloat16(ho);
        g_WoT_lo[n * 256 + k] = __float2bfloat16(o - ho);
    }
    if (idx < 256 * 512) {
        int n = idx >> 9, k = idx & 511;
        float v = 0.f;
        if (n < 128)      v = Wso[k * 128 + n];
        else if (n < 192) v = Waw[k * 64 + (n - 128)];
        float h = bf_round(v);
        g_W2T_hi[n * 512 + k] = __float2bfloat16(h);
        g_W2T_lo[n * 512 + k] = __float2bfloat16(v - h);
    }
    if (idx < 256) {
        float b = 0.f;
        if (idx < 128)      b = bso[idx];
        else if (idx < 192) b = baw[idx - 128];
        g_bias2[idx] = b;
    }
}

// ============================ mma.sync GEMM ================================
// D = A(fp32, split to bf16 hi/lo) @ B^T(pre-split bf16).
// Block tile 128x128, 8 warps (4x2), warp tile 32x64, k-chunk 32, 2-stage.
#define ROWB   80
#define T_AHI  0
#define T_ALO  10240
#define T_BHI  20480
#define T_BLO  30720
#define STAGEB 40960
#define SMEM_DYN_BYTES (2 * STAGEB)

template <int MODE>
__global__ __launch_bounds__(256, 1)
void tsa_gemm(const float* __restrict__ A, const float* __restrict__ Aq,
              const float* __restrict__ bias, const float* __restrict__ resid,
              float* __restrict__ outp)
{
    constexpr int KT   = (MODE == 1) ? 512 : 256;
    constexpr int MTOT = (MODE == 0) ? 80000 : 40000;
    constexpr int NC   = KT / 32;

    extern __shared__ char sm[];
    const uint32_t smb = smem_u32(sm);

    const int tid  = threadIdx.x;
    const int lane = tid & 31;
    const int wid  = tid >> 5;
    const int wm   = wid >> 1;
    const int wn   = wid & 1;
    const int m0   = blockIdx.x * 128;
    const int n0   = blockIdx.y * 128;

    const float* Abase = (MODE == 2) ? g_attn : A;
    const __nv_bfloat16* BTh = (MODE == 0) ? g_WvT_hi : (MODE == 1) ? g_W2T_hi : g_WoT_hi;
    const __nv_bfloat16* BTl = (MODE == 0) ? g_WvT_lo : (MODE == 1) ? g_W2T_lo : g_WoT_lo;

    const int arow = tid >> 1;
    const int akh  = (tid & 1) * 16;
    int agrow = m0 + arow; if (agrow > MTOT - 1) agrow = MTOT - 1;

    const int brow  = tid >> 1;
    const int bseg0 = (tid & 1) * 2;
    const int bn    = n0 + brow;

    const int grp = lane >> 3, r = lane & 7;
    const uint32_t a_off = (uint32_t)((wm * 32 + ((grp & 1) << 3) + r) * ROWB + (grp >> 1) * 16);
    const uint32_t b_off = (uint32_t)((wn * 64 + ((grp >> 1) << 3) + r) * ROWB + (grp & 1) * 16);

    float acc[2][8][4];
    #pragma unroll
    for (int mt = 0; mt < 2; mt++)
        #pragma unroll
        for (int nt = 0; nt < 8; nt++)
            #pragma unroll
            for (int i = 0; i < 4; i++) acc[mt][nt][i] = 0.f;

    float av[16];

    {
        const float4* p = (const float4*)(Abase + (size_t)agrow * 256 + akh);
        #pragma unroll
        for (int j = 0; j < 4; j++) {
            float4 v = p[j];
            av[j*4+0] = v.x; av[j*4+1] = v.y; av[j*4+2] = v.z; av[j*4+3] = v.w;
        }
        const __nv_bfloat16* gh = BTh + (size_t)bn * KT + bseg0 * 8;
        const __nv_bfloat16* gl = BTl + (size_t)bn * KT + bseg0 * 8;
        uint32_t sh = smb + T_BHI + brow * ROWB + bseg0 * 16;
        uint32_t sl = sh + (T_BLO - T_BHI);
        CP16(sh, gh); CP16(sh + 16, gh + 8);
        CP16(sl, gl); CP16(sl + 16, gl + 8);
        CP_COMMIT();

        uint32_t hp[8], lp[8];
        #pragma unroll
        for (int j = 0; j < 8; j++) {
            float x0 = av[2*j], x1 = av[2*j+1];
            float h0 = bf_round(x0), h1 = bf_round(x1);
            hp[j] = pack_bf16x2(h1, h0);
            lp[j] = pack_bf16x2(x1 - h1, x0 - h0);
        }
        char* dst = sm + arow * ROWB + akh * 2;
        *(uint4*)(dst + T_AHI)      = ((uint4*)hp)[0];
        *(uint4*)(dst + T_AHI + 16) = ((uint4*)hp)[1];
        *(uint4*)(dst + T_ALO)      = ((uint4*)lp)[0];
        *(uint4*)(dst + T_ALO + 16) = ((uint4*)lp)[1];
        CP_WAIT0();
        __syncthreads();
    }

    for (int c = 0; c < NC; c++) {
        const int stg  = c & 1;
        const int nstg = stg ^ 1;
        const bool more = (c + 1 < NC);

        if (more) {
            int k0 = (c + 1) * 32;
            const float* src = Abase; int kl = k0;
            if (MODE == 1 && kl >= 256) { src = Aq; kl -= 256; }
            const float4* p = (const float4*)(src + (size_t)agrow * 256 + kl + akh);
            #pragma unroll
            for (int j = 0; j < 4; j++) {
                float4 v = p[j];
                av[j*4+0] = v.x; av[j*4+1] = v.y; av[j*4+2] = v.z; av[j*4+3] = v.w;
            }
            const __nv_bfloat16* gh = BTh + (size_t)bn * KT + k0 + bseg0 * 8;
            const __nv_bfloat16* gl = BTl + (size_t)bn * KT + k0 + bseg0 * 8;
            uint32_t sh = smb + nstg * STAGEB + T_BHI + brow * ROWB + bseg0 * 16;
            uint32_t sl = sh + (T_BLO - T_BHI);
            CP16(sh, gh); CP16(sh + 16, gh + 8);
            CP16(sl, gl); CP16(sl + 16, gl + 8);
            CP_COMMIT();
        }

        const uint32_t base = smb + stg * STAGEB;
        #pragma unroll
        for (int ks = 0; ks < 32; ks += 16) {
            uint32_t ah[2][4], al[2][4];
            #pragma unroll
            for (int mt = 0; mt < 2; mt++) {
                ldsm4(ah[mt], base + T_AHI + a_off + mt * (16 * ROWB) + ks * 2);
                ldsm4(al[mt], base + T_ALO + a_off + mt * (16 * ROWB) + ks * 2);
            }
            uint32_t bh[4][4], bl[4][4];
            #pragma unroll
            for (int pr = 0; pr < 4; pr++) {
                ldsm4(bh[pr], base + T_BHI + b_off + pr * (16 * ROWB) + ks * 2);
                ldsm4(bl[pr], base + T_BLO + b_off + pr * (16 * ROWB) + ks * 2);
            }
            #pragma unroll
            for (int mt = 0; mt < 2; mt++)
                #pragma unroll
                for (int nt = 0; nt < 8; nt++) {
                    uint32_t bh0 = bh[nt >> 1][(nt & 1) * 2], bh1 = bh[nt >> 1][(nt & 1) * 2 + 1];
                    uint32_t bl0 = bl[nt >> 1][(nt & 1) * 2], bl1 = bl[nt >> 1][(nt & 1) * 2 + 1];
                    mma16816(acc[mt][nt], ah[mt], bh0, bh1);
                    mma16816(acc[mt][nt], ah[mt], bl0, bl1);
                    mma16816(acc[mt][nt], al[mt], bh0, bh1);
                }
        }

        if (more) {
            uint32_t hp[8], lp[8];
            #pragma unroll
            for (int j = 0; j < 8; j++) {
                float x0 = av[2*j], x1 = av[2*j+1];
                float h0 = bf_round(x0), h1 = bf_round(x1);
                hp[j] = pack_bf16x2(h1, h0);
                lp[j] = pack_bf16x2(x1 - h1, x0 - h0);
            }
            char* dst = sm + nstg * STAGEB + arow * ROWB + akh * 2;
            *(uint4*)(dst + T_AHI)      = ((uint4*)hp)[0];
            *(uint4*)(dst + T_AHI + 16) = ((uint4*)hp)[1];
            *(uint4*)(dst + T_ALO)      = ((uint4*)lp)[0];
            *(uint4*)(dst + T_ALO + 16) = ((uint4*)lp)[1];
            CP_WAIT0();
            __syncthreads();
        }
    }

    #pragma unroll
    for (int mt = 0; mt < 2; mt++) {
        const int rbase = m0 + wm * 32 + mt * 16 + (lane >> 2);
        #pragma unroll
        for (int nt = 0; nt < 8; nt++) {
            const int gn = n0 + wn * 64 + nt * 8 + (lane & 3) * 2;
            #pragma unroll
            for (int hf = 0; hf < 2; hf++) {
                const int row = rbase + hf * 8;
                if (row >= MTOT) continue;
                float c0 = acc[mt][nt][hf * 2], c1 = acc[mt][nt][hf * 2 + 1];
                if (MODE == 0) {
                    float2 o = make_float2(c0 + bias[gn], c1 + bias[gn + 1]);
                    *(float2*)&g_value[(size_t)row * 256 + gn] = o;
                } else if (MODE == 1) {
                    if (gn >= 192) continue;
                    float2 o = make_float2(c0 + g_bias2[gn], c1 + g_bias2[gn + 1]);
                    if (gn < 128) *(float2*)&g_so[(size_t)row * 128 + gn] = o;
                    else          *(float2*)&g_aw[(size_t)row * 64 + (gn - 128)] = o;
                } else {
                    float2 q = *(const float2*)&resid[(size_t)row * 256 + gn];
                    float2 o = make_float2(c0 + bias[gn] + q.x, c1 + bias[gn + 1] + q.y);
                    *(float2*)&outp[(size_t)row * 256 + gn] = o;
                }
            }
        }
    }
}

// ============================ sampling v2 ==================================
// One warp covers (q, 4 heads). Lane = (head_sub = lane>>3, c4 = (lane&7)*4).
// Each lane accumulates a float4 (4 contiguous channels of its head).
// Validity folded into bilinear weights; addresses clamped; 32-bit offsets.
__global__ __launch_bounds__(256)
void sample_kernel(const float* __restrict__ ref2d)
{
    const int gw = blockIdx.x * 8 + (threadIdx.x >> 5);   // 0 .. 79999
    const int q  = gw >> 1;
    const int lane = threadIdx.x & 31;
    const int h  = ((gw & 1) << 2) + (lane >> 3);         // head 0..7
    const int c4 = (lane & 7) << 2;                        // channel 0,4,..,28

    const float* __restrict__ so_q = &g_so[(size_t)q * 128];
    const float* __restrict__ aw_q = &g_aw[(size_t)q * 64];

    float4 acc = make_float4(0.f, 0.f, 0.f, 0.f);

    #pragma unroll
    for (int b = 0; b < NBQc; b++) {
        const int awbase = (h * 2 + b) * 4;
        float a0 = aw_q[awbase + 0], a1 = aw_q[awbase + 1];
        float a2 = aw_q[awbase + 2], a3 = aw_q[awbase + 3];
        float mx = fmaxf(fmaxf(a0, a1), fmaxf(a2, a3));
        float e0 = __expf(a0 - mx), e1 = __expf(a1 - mx);
        float e2 = __expf(a2 - mx), e3 = __expf(a3 - mx);
        float inv = 1.f / (e0 + e1 + e2 + e3);
        float wts[4] = {e0 * inv, e1 * inv, e2 * inv, e3 * inv};

        const float rx = ref2d[((size_t)b * NQc + q) * 2 + 0];
        const float ry = ref2d[((size_t)b * NQc + q) * 2 + 1];
        const float* __restrict__ vbase = g_value + (size_t)b * (NQc * EDc) + (h << 5) + c4;

        #pragma unroll
        for (int p = 0; p < NPc; p++) {
            const int j = (awbase + p) * 2;
            float x = fmaf(so_q[j + 0], 1.0f, rx * (float)Wc) - 0.5f;
            float y = fmaf(so_q[j + 1], 1.0f, ry * (float)Hc) - 0.5f;
            float x0f = floorf(x), y0f = floorf(y);
            float wx = x - x0f, wy = y - y0f;
            int ix0 = (int)x0f, iy0 = (int)y0f;

            // validity masks folded into weights
            float mx0 = ((unsigned)ix0       < (unsigned)Wc) ? 1.f : 0.f;
            float mx1 = ((unsigned)(ix0 + 1) < (unsigned)Wc) ? 1.f : 0.f;
            float my0 = ((unsigned)iy0       < (unsigned)Hc) ? 1.f : 0.f;
            float my1 = ((unsigned)(iy0 + 1) < (unsigned)Hc) ? 1.f : 0.f;

            float w00 = (1.f - wx) * (1.f - wy) * mx0 * my0;
            float w10 = wx * (1.f - wy) * mx1 * my0;
            float w01 = (1.f - wx) * wy * mx0 * my1;
            float w11 = wx * wy * mx1 * my1;

            // clamped pixel indices (loads always in-bounds)
            int ix0c = min(max(ix0, 0), Wc - 1);
            int ix1c = min(max(ix0 + 1, 0), Wc - 1);
            int iy0c = min(max(iy0, 0), Hc - 1);
            int iy1c = min(max(iy0 + 1, 0), Hc - 1);

            uint32_t r0 = (uint32_t)(iy0c * Wc) << 8;   // *256 floats
            uint32_t r1 = (uint32_t)(iy1c * Wc) << 8;
            uint32_t cx0 = (uint32_t)ix0c << 8;
            uint32_t cx1 = (uint32_t)ix1c << 8;

            float4 v00 = *(const float4*)(vbase + r0 + cx0);
            float4 v10 = *(const float4*)(vbase + r0 + cx1);
            float4 v01 = *(const float4*)(vbase + r1 + cx0);
            float4 v11 = *(const float4*)(vbase + r1 + cx1);

            float wt = wts[p];
            acc.x = fmaf(wt, w00*v00.x + w10*v10.x + w01*v01.x + w11*v11.x, acc.x);
            acc.y = fmaf(wt, w00*v00.y + w10*v10.y + w01*v01.y + w11*v11.y, acc.y);
            acc.z = fmaf(wt, w00*v00.z + w10*v10.z + w01*v01.z + w11*v11.z, acc.z);
            acc.w = fmaf(wt, w00*v00.w + w10*v10.w + w01*v01.w + w11*v11.w, acc.w);
        }
    }
    float4 o = make_float4(0.5f * acc.x, 0.5f * acc.y, 0.5f * acc.z, 0.5f * acc.w);
    *(float4*)&g_attn[(size_t)q * EDc + (h << 5) + c4] = o;
}

// ============================================================================
extern "C" void kernel_launch(void* const* d_in, const int* in_sizes, int n_in,
                              void* d_out, int out_size)
{
    const float* query    = (const float*)d_in[0];
    const float* prev_bev = (const float*)d_in[1];
    const float* ref2d    = (const float*)d_in[3];
    const float* Wv       = (const float*)d_in[4];
    const float* bv       = (const float*)d_in[5];
    const float* Wso      = (const float*)d_in[6];
    const float* bso      = (const float*)d_in[7];
    const float* Waw      = (const float*)d_in[8];
    const float* baw      = (const float*)d_in[9];
    const float* Wo       = (const float*)d_in[10];
    const float* bo       = (const float*)d_in[11];
    float* out = (float*)d_out;

    cudaFuncSetAttribute(tsa_gemm<0>, cudaFuncAttributeMaxDynamicSharedMemorySize, SMEM_DYN_BYTES);
    cudaFuncSetAttribute(tsa_gemm<1>, cudaFuncAttributeMaxDynamicSharedMemorySize, SMEM_DYN_BYTES);
    cudaFuncSetAttribute(tsa_gemm<2>, cudaFuncAttributeMaxDynamicSharedMemorySize, SMEM_DYN_BYTES);

    prep_weights<<<512, 256>>>(Wv, Wso, Waw, Wo, bso, baw);

    // 1) value projection: 80000 x 256 x 256
    tsa_gemm<0><<<dim3(625, 2), 256, SMEM_DYN_BYTES>>>(prev_bev, nullptr, bv, nullptr, nullptr);

    // 2) offsets + logits: 40000 x 512 x 192
    tsa_gemm<1><<<dim3(313, 2), 256, SMEM_DYN_BYTES>>>(prev_bev, query, nullptr, nullptr, nullptr);

    // 3) softmax + bilinear sampling (1 warp per (q, 4 heads))
    sample_kernel<<<NQc * 2 / 8, 256>>>(ref2d);

    // 4) output projection + residual: 40000 x 256 x 256
    tsa_gemm<2><<<dim3(313, 2), 256, SMEM_DYN_BYTES>>>(nullptr, nullptr, bo, query, out);
}

// round 6
// speedup vs baseline: 2.4637x; 1.0838x over previous
#include <cuda_runtime.h>
#include <cuda_bf16.h>
#include <cuda_fp16.h>
#include <cstdint>
#include <math.h>

#define NQc   40000
#define EDc   256
#define NHc   8
#define NBQc  2
#define NPc   4
#define Hc    200
#define Wc    200

// ---------------- scratch (device globals; no allocation allowed) ----------
__device__ __half g_value[NBQc * NQc * EDc];  // (2,40000,256) fp16, 41 MB
__device__ float g_so[NQc * 128];
__device__ float g_aw[NQc * 64];
__device__ float g_attn[NQc * EDc];

// pre-transposed, bf16-split weights: [N][K] row-major
__device__ __nv_bfloat16 g_WvT_hi[256 * 256], g_WvT_lo[256 * 256];
__device__ __nv_bfloat16 g_WoT_hi[256 * 256], g_WoT_lo[256 * 256];
__device__ __nv_bfloat16 g_W2T_hi[256 * 512], g_W2T_lo[256 * 512]; // n<128: Wso, 128..191: Waw, >=192: 0
__device__ float g_bias2[256];

// ============================ helpers ======================================
__device__ __forceinline__ uint32_t smem_u32(const void* p) {
    uint32_t a;
    asm("{ .reg .u64 t; cvta.to.shared.u64 t, %1; cvt.u32.u64 %0, t; }" : "=r"(a) : "l"(p));
    return a;
}
__device__ __forceinline__ float bf_round(float x) {
    return __bfloat162float(__float2bfloat16(x));
}
__device__ __forceinline__ uint32_t pack_bf16x2(float hi, float lo) {
    uint32_t r;
    asm("cvt.rn.bf16x2.f32 %0, %1, %2;" : "=r"(r) : "f"(hi), "f"(lo));
    return r;
}
__device__ __forceinline__ void ldsm4(uint32_t* r, uint32_t addr) {
    asm volatile("ldmatrix.sync.aligned.m8n8.x4.shared.b16 {%0,%1,%2,%3}, [%4];"
                 : "=r"(r[0]), "=r"(r[1]), "=r"(r[2]), "=r"(r[3]) : "r"(addr));
}
__device__ __forceinline__ void mma16816(float* c, const uint32_t* a, uint32_t b0, uint32_t b1) {
    asm volatile("mma.sync.aligned.m16n8k16.row.col.f32.bf16.bf16.f32 "
                 "{%0,%1,%2,%3}, {%4,%5,%6,%7}, {%8,%9}, {%0,%1,%2,%3};"
                 : "+f"(c[0]), "+f"(c[1]), "+f"(c[2]), "+f"(c[3])
                 : "r"(a[0]), "r"(a[1]), "r"(a[2]), "r"(a[3]), "r"(b0), "r"(b1));
}
#define CP16(smaddr, gptr) \
    asm volatile("cp.async.cg.shared.global [%0], [%1], 16;" :: "r"(smaddr), "l"(gptr))
#define CP_COMMIT() asm volatile("cp.async.commit_group;" ::: "memory")
#define CP_WAIT0()  asm volatile("cp.async.wait_group 0;" ::: "memory")

// ============================ weight prep ==================================
__global__ void prep_weights(const float* __restrict__ Wv, const float* __restrict__ Wso,
                             const float* __restrict__ Waw, const float* __restrict__ Wo,
                             const float* __restrict__ bso, const float* __restrict__ baw)
{
    int idx = blockIdx.x * 256 + threadIdx.x;
    if (idx < 256 * 256) {
        int n = idx >> 8, k = idx & 255;
        float v = Wv[k * 256 + n];
        float h = bf_round(v);
        g_WvT_hi[n * 256 + k] = __float2bfloat16(h);
        g_WvT_lo[n * 256 + k] = __float2bfloat16(v - h);
        float o = Wo[k * 256 + n];
        float ho = bf_round(o);
        g_WoT_hi[n * 256 + k] = __float2bfloat16(ho);
        g_WoT_lo[n * 256 + k] = __float2bfloat16(o - ho);
    }
    if (idx < 256 * 512) {
        int n = idx >> 9, k = idx & 511;
        float v = 0.f;
        if (n < 128)      v = Wso[k * 128 + n];
        else if (n < 192) v = Waw[k * 64 + (n - 128)];
        float h = bf_round(v);
        g_W2T_hi[n * 512 + k] = __float2bfloat16(h);
        g_W2T_lo[n * 512 + k] = __float2bfloat16(v - h);
    }
    if (idx < 256) {
        float b = 0.f;
        if (idx < 128)      b = bso[idx];
        else if (idx < 192) b = baw[idx - 128];
        g_bias2[idx] = b;
    }
}

// ============================ mma.sync GEMM ================================
// D = A(fp32, split to bf16 hi/lo) @ B^T(pre-split bf16).
// Block tile 128x128, 8 warps (4x2), warp tile 32x64, k-chunk 32, 2-stage.
#define ROWB   80
#define T_AHI  0
#define T_ALO  10240
#define T_BHI  20480
#define T_BLO  30720
#define STAGEB 40960
#define SMEM_DYN_BYTES (2 * STAGEB)

template <int MODE>
__global__ __launch_bounds__(256, 1)
void tsa_gemm(const float* __restrict__ A, const float* __restrict__ Aq,
              const float* __restrict__ bias, const float* __restrict__ resid,
              float* __restrict__ outp)
{
    constexpr int KT   = (MODE == 1) ? 512 : 256;
    constexpr int MTOT = (MODE == 0) ? 80000 : 40000;
    constexpr int NC   = KT / 32;

    extern __shared__ char sm[];
    const uint32_t smb = smem_u32(sm);

    const int tid  = threadIdx.x;
    const int lane = tid & 31;
    const int wid  = tid >> 5;
    const int wm   = wid >> 1;
    const int wn   = wid & 1;
    const int m0   = blockIdx.x * 128;
    const int n0   = blockIdx.y * 128;

    const float* Abase = (MODE == 2) ? g_attn : A;
    const __nv_bfloat16* BTh = (MODE == 0) ? g_WvT_hi : (MODE == 1) ? g_W2T_hi : g_WoT_hi;
    const __nv_bfloat16* BTl = (MODE == 0) ? g_WvT_lo : (MODE == 1) ? g_W2T_lo : g_WoT_lo;

    const int arow = tid >> 1;
    const int akh  = (tid & 1) * 16;
    int agrow = m0 + arow; if (agrow > MTOT - 1) agrow = MTOT - 1;

    const int brow  = tid >> 1;
    const int bseg0 = (tid & 1) * 2;
    const int bn    = n0 + brow;

    const int grp = lane >> 3, r = lane & 7;
    const uint32_t a_off = (uint32_t)((wm * 32 + ((grp & 1) << 3) + r) * ROWB + (grp >> 1) * 16);
    const uint32_t b_off = (uint32_t)((wn * 64 + ((grp >> 1) << 3) + r) * ROWB + (grp & 1) * 16);

    float acc[2][8][4];
    #pragma unroll
    for (int mt = 0; mt < 2; mt++)
        #pragma unroll
        for (int nt = 0; nt < 8; nt++)
            #pragma unroll
            for (int i = 0; i < 4; i++) acc[mt][nt][i] = 0.f;

    float av[16];

    {
        const float4* p = (const float4*)(Abase + (size_t)agrow * 256 + akh);
        #pragma unroll
        for (int j = 0; j < 4; j++) {
            float4 v = p[j];
            av[j*4+0] = v.x; av[j*4+1] = v.y; av[j*4+2] = v.z; av[j*4+3] = v.w;
        }
        const __nv_bfloat16* gh = BTh + (size_t)bn * KT + bseg0 * 8;
        const __nv_bfloat16* gl = BTl + (size_t)bn * KT + bseg0 * 8;
        uint32_t sh = smb + T_BHI + brow * ROWB + bseg0 * 16;
        uint32_t sl = sh + (T_BLO - T_BHI);
        CP16(sh, gh); CP16(sh + 16, gh + 8);
        CP16(sl, gl); CP16(sl + 16, gl + 8);
        CP_COMMIT();

        uint32_t hp[8], lp[8];
        #pragma unroll
        for (int j = 0; j < 8; j++) {
            float x0 = av[2*j], x1 = av[2*j+1];
            float h0 = bf_round(x0), h1 = bf_round(x1);
            hp[j] = pack_bf16x2(h1, h0);
            lp[j] = pack_bf16x2(x1 - h1, x0 - h0);
        }
        char* dst = sm + arow * ROWB + akh * 2;
        *(uint4*)(dst + T_AHI)      = ((uint4*)hp)[0];
        *(uint4*)(dst + T_AHI + 16) = ((uint4*)hp)[1];
        *(uint4*)(dst + T_ALO)      = ((uint4*)lp)[0];
        *(uint4*)(dst + T_ALO + 16) = ((uint4*)lp)[1];
        CP_WAIT0();
        __syncthreads();
    }

    for (int c = 0; c < NC; c++) {
        const int stg  = c & 1;
        const int nstg = stg ^ 1;
        const bool more = (c + 1 < NC);

        if (more) {
            int k0 = (c + 1) * 32;
            const float* src = Abase; int kl = k0;
            if (MODE == 1 && kl >= 256) { src = Aq; kl -= 256; }
            const float4* p = (const float4*)(src + (size_t)agrow * 256 + kl + akh);
            #pragma unroll
            for (int j = 0; j < 4; j++) {
                float4 v = p[j];
                av[j*4+0] = v.x; av[j*4+1] = v.y; av[j*4+2] = v.z; av[j*4+3] = v.w;
            }
            const __nv_bfloat16* gh = BTh + (size_t)bn * KT + k0 + bseg0 * 8;
            const __nv_bfloat16* gl = BTl + (size_t)bn * KT + k0 + bseg0 * 8;
            uint32_t sh = smb + nstg * STAGEB + T_BHI + brow * ROWB + bseg0 * 16;
            uint32_t sl = sh + (T_BLO - T_BHI);
            CP16(sh, gh); CP16(sh + 16, gh + 8);
            CP16(sl, gl); CP16(sl + 16, gl + 8);
            CP_COMMIT();
        }

        const uint32_t base = smb + stg * STAGEB;
        #pragma unroll
        for (int ks = 0; ks < 32; ks += 16) {
            uint32_t ah[2][4], al[2][4];
            #pragma unroll
            for (int mt = 0; mt < 2; mt++) {
                ldsm4(ah[mt], base + T_AHI + a_off + mt * (16 * ROWB) + ks * 2);
                ldsm4(al[mt], base + T_ALO + a_off + mt * (16 * ROWB) + ks * 2);
            }
            uint32_t bh[4][4], bl[4][4];
            #pragma unroll
            for (int pr = 0; pr < 4; pr++) {
                ldsm4(bh[pr], base + T_BHI + b_off + pr * (16 * ROWB) + ks * 2);
                ldsm4(bl[pr], base + T_BLO + b_off + pr * (16 * ROWB) + ks * 2);
            }
            #pragma unroll
            for (int mt = 0; mt < 2; mt++)
                #pragma unroll
                for (int nt = 0; nt < 8; nt++) {
                    uint32_t bh0 = bh[nt >> 1][(nt & 1) * 2], bh1 = bh[nt >> 1][(nt & 1) * 2 + 1];
                    uint32_t bl0 = bl[nt >> 1][(nt & 1) * 2], bl1 = bl[nt >> 1][(nt & 1) * 2 + 1];
                    mma16816(acc[mt][nt], ah[mt], bh0, bh1);
                    mma16816(acc[mt][nt], ah[mt], bl0, bl1);
                    mma16816(acc[mt][nt], al[mt], bh0, bh1);
                }
        }

        if (more) {
            uint32_t hp[8], lp[8];
            #pragma unroll
            for (int j = 0; j < 8; j++) {
                float x0 = av[2*j], x1 = av[2*j+1];
                float h0 = bf_round(x0), h1 = bf_round(x1);
                hp[j] = pack_bf16x2(h1, h0);
                lp[j] = pack_bf16x2(x1 - h1, x0 - h0);
            }
            char* dst = sm + nstg * STAGEB + arow * ROWB + akh * 2;
            *(uint4*)(dst + T_AHI)      = ((uint4*)hp)[0];
            *(uint4*)(dst + T_AHI + 16) = ((uint4*)hp)[1];
            *(uint4*)(dst + T_ALO)      = ((uint4*)lp)[0];
            *(uint4*)(dst + T_ALO + 16) = ((uint4*)lp)[1];
            CP_WAIT0();
            __syncthreads();
        }
    }

    #pragma unroll
    for (int mt = 0; mt < 2; mt++) {
        const int rbase = m0 + wm * 32 + mt * 16 + (lane >> 2);
        #pragma unroll
        for (int nt = 0; nt < 8; nt++) {
            const int gn = n0 + wn * 64 + nt * 8 + (lane & 3) * 2;
            #pragma unroll
            for (int hf = 0; hf < 2; hf++) {
                const int row = rbase + hf * 8;
                if (row >= MTOT) continue;
                float c0 = acc[mt][nt][hf * 2], c1 = acc[mt][nt][hf * 2 + 1];
                if (MODE == 0) {
                    __half2 o = __floats2half2_rn(c0 + bias[gn], c1 + bias[gn + 1]);
                    *(__half2*)&g_value[(size_t)row * 256 + gn] = o;
                } else if (MODE == 1) {
                    if (gn >= 192) continue;
                    float2 o = make_float2(c0 + g_bias2[gn], c1 + g_bias2[gn + 1]);
                    if (gn < 128) *(float2*)&g_so[(size_t)row * 128 + gn] = o;
                    else          *(float2*)&g_aw[(size_t)row * 64 + (gn - 128)] = o;
                } else {
                    float2 q = *(const float2*)&resid[(size_t)row * 256 + gn];
                    float2 o = make_float2(c0 + bias[gn] + q.x, c1 + bias[gn + 1] + q.y);
                    *(float2*)&outp[(size_t)row * 256 + gn] = o;
                }
            }
        }
    }
}

// ============================ sampling v3 ==================================
// One warp covers (q, 4 heads). Lane: head = lane>>3, 4 channels = (lane&7)*4.
// g_value is fp16: each gather is uint2 (4 halfs). Per bq, all 16 gathers are
// issued before any weighting math (max MLP).
__global__ __launch_bounds__(256)
void sample_kernel(const float* __restrict__ ref2d)
{
    const int gw = blockIdx.x * 8 + (threadIdx.x >> 5);   // 0 .. 79999
    const int q  = gw >> 1;
    const int lane = threadIdx.x & 31;
    const int h  = ((gw & 1) << 2) + (lane >> 3);         // head 0..7
    const int c4 = (lane & 7) << 2;                        // channel 0,4,..,28

    const float* __restrict__ so_q = &g_so[(size_t)q * 128];
    const float* __restrict__ aw_q = &g_aw[(size_t)q * 64];

    float4 acc = make_float4(0.f, 0.f, 0.f, 0.f);

    #pragma unroll
    for (int b = 0; b < NBQc; b++) {
        const int awbase = (h * 2 + b) * 4;
        float a0 = aw_q[awbase + 0], a1 = aw_q[awbase + 1];
        float a2 = aw_q[awbase + 2], a3 = aw_q[awbase + 3];
        float mx = fmaxf(fmaxf(a0, a1), fmaxf(a2, a3));
        float e0 = __expf(a0 - mx), e1 = __expf(a1 - mx);
        float e2 = __expf(a2 - mx), e3 = __expf(a3 - mx);
        float inv = 1.f / (e0 + e1 + e2 + e3);
        float wts[4] = {e0 * inv, e1 * inv, e2 * inv, e3 * inv};

        const float rx = ref2d[((size_t)b * NQc + q) * 2 + 0];
        const float ry = ref2d[((size_t)b * NQc + q) * 2 + 1];
        const __half* __restrict__ vbase =
            g_value + (size_t)b * (NQc * EDc) + (h << 5) + c4;

        // phase 1: addresses + bilinear weights for all 4 points
        uint32_t offs[4][4];
        float    w[4][4];
        #pragma unroll
        for (int p = 0; p < NPc; p++) {
            const int j = (awbase + p) * 2;
            float x = fmaf(so_q[j + 0], 1.0f, rx * (float)Wc) - 0.5f;
            float y = fmaf(so_q[j + 1], 1.0f, ry * (float)Hc) - 0.5f;
            float x0f = floorf(x), y0f = floorf(y);
            float wx = x - x0f, wy = y - y0f;
            int ix0 = (int)x0f, iy0 = (int)y0f;

            float mx0 = ((unsigned)ix0       < (unsigned)Wc) ? 1.f : 0.f;
            float mx1 = ((unsigned)(ix0 + 1) < (unsigned)Wc) ? 1.f : 0.f;
            float my0 = ((unsigned)iy0       < (unsigned)Hc) ? 1.f : 0.f;
            float my1 = ((unsigned)(iy0 + 1) < (unsigned)Hc) ? 1.f : 0.f;

            float wt = wts[p];
            w[p][0] = (1.f - wx) * (1.f - wy) * mx0 * my0 * wt;
            w[p][1] = wx * (1.f - wy) * mx1 * my0 * wt;
            w[p][2] = (1.f - wx) * wy * mx0 * my1 * wt;
            w[p][3] = wx * wy * mx1 * my1 * wt;

            int ix0c = min(max(ix0, 0), Wc - 1);
            int ix1c = min(max(ix0 + 1, 0), Wc - 1);
            int iy0c = min(max(iy0, 0), Hc - 1);
            int iy1c = min(max(iy0 + 1, 0), Hc - 1);

            uint32_t r0 = (uint32_t)(iy0c * Wc) << 8;   // *256 halfs
            uint32_t r1 = (uint32_t)(iy1c * Wc) << 8;
            uint32_t cx0 = (uint32_t)ix0c << 8;
            uint32_t cx1 = (uint32_t)ix1c << 8;
            offs[p][0] = r0 + cx0;
            offs[p][1] = r0 + cx1;
            offs[p][2] = r1 + cx0;
            offs[p][3] = r1 + cx1;
        }

        // phase 2: issue all 16 gathers (uint2 = 4 fp16 channels)
        uint2 d[4][4];
        #pragma unroll
        for (int p = 0; p < NPc; p++)
            #pragma unroll
            for (int c = 0; c < 4; c++)
                d[p][c] = *(const uint2*)(vbase + offs[p][c]);

        // phase 3: convert + weighted accumulate
        #pragma unroll
        for (int p = 0; p < NPc; p++) {
            #pragma unroll
            for (int c = 0; c < 4; c++) {
                float2 lo = __half22float2(*(const __half2*)&d[p][c].x);
                float2 hi = __half22float2(*(const __half2*)&d[p][c].y);
                float ww = w[p][c];
                acc.x = fmaf(ww, lo.x, acc.x);
                acc.y = fmaf(ww, lo.y, acc.y);
                acc.z = fmaf(ww, hi.x, acc.z);
                acc.w = fmaf(ww, hi.y, acc.w);
            }
        }
    }
    float4 o = make_float4(0.5f * acc.x, 0.5f * acc.y, 0.5f * acc.z, 0.5f * acc.w);
    *(float4*)&g_attn[(size_t)q * EDc + (h << 5) + c4] = o;
}

// ============================================================================
extern "C" void kernel_launch(void* const* d_in, const int* in_sizes, int n_in,
                              void* d_out, int out_size)
{
    const float* query    = (const float*)d_in[0];
    const float* prev_bev = (const float*)d_in[1];
    const float* ref2d    = (const float*)d_in[3];
    const float* Wv       = (const float*)d_in[4];
    const float* bv       = (const float*)d_in[5];
    const float* Wso      = (const float*)d_in[6];
    const float* bso      = (const float*)d_in[7];
    const float* Waw      = (const float*)d_in[8];
    const float* baw      = (const float*)d_in[9];
    const float* Wo       = (const float*)d_in[10];
    const float* bo       = (const float*)d_in[11];
    float* out = (float*)d_out;

    cudaFuncSetAttribute(tsa_gemm<0>, cudaFuncAttributeMaxDynamicSharedMemorySize, SMEM_DYN_BYTES);
    cudaFuncSetAttribute(tsa_gemm<1>, cudaFuncAttributeMaxDynamicSharedMemorySize, SMEM_DYN_BYTES);
    cudaFuncSetAttribute(tsa_gemm<2>, cudaFuncAttributeMaxDynamicSharedMemorySize, SMEM_DYN_BYTES);

    prep_weights<<<512, 256>>>(Wv, Wso, Waw, Wo, bso, baw);

    // 1) value projection: 80000 x 256 x 256 (fp16 output)
    tsa_gemm<0><<<dim3(625, 2), 256, SMEM_DYN_BYTES>>>(prev_bev, nullptr, bv, nullptr, nullptr);

    // 2) offsets + logits: 40000 x 512 x 192
    tsa_gemm<1><<<dim3(313, 2), 256, SMEM_DYN_BYTES>>>(prev_bev, query, nullptr, nullptr, nullptr);

    // 3) softmax + bilinear sampling (fp16 gathers, batched MLP)
    sample_kernel<<<NQc * 2 / 8, 256>>>(ref2d);

    // 4) output projection + residual: 40000 x 256 x 256
    tsa_gemm<2><<<dim3(313, 2), 256, SMEM_DYN_BYTES>>>(nullptr, nullptr, bo, query, out);
}

// round 13
// speedup vs baseline: 2.7916x; 1.1331x over previous
#include <cuda_runtime.h>
#include <cuda_bf16.h>
#include <cuda_fp16.h>
#include <cstdint>
#include <math.h>

#define NQc   40000
#define EDc   256
#define NHc   8
#define NBQc  2
#define NPc   4
#define Hc    200
#define Wc    200

// ---------------- scratch (device globals) ---------------------------------
// NOTE: total static footprint must stay at the round-6 level (~108 MiB).
// Exceeding ~128 MiB makes the driver grow the device-globals arena during
// the correctness run, tripping the harness allocation guard (rounds 9/11).
__device__ __half g_value[NBQc * NQc * EDc];  // 41.0 MB fp16
__device__ float g_so[NQc * 128];             // 20.5 MB
__device__ float g_aw[NQc * 64];              // 10.2 MB
__device__ float g_attn[NQc * EDc];           // 41.0 MB

// pre-transposed, bf16-split weights: [N][K] row-major (~1.1 MB)
__device__ __nv_bfloat16 g_WvT_hi[256 * 256], g_WvT_lo[256 * 256];
__device__ __nv_bfloat16 g_WoT_hi[256 * 256], g_WoT_lo[256 * 256];
__device__ __nv_bfloat16 g_W2T_hi[256 * 512], g_W2T_lo[256 * 512];
__device__ float g_bias2[256];

// ============================ helpers ======================================
__device__ __forceinline__ uint32_t smem_u32(const void* p) {
    uint32_t a;
    asm("{ .reg .u64 t; cvta.to.shared.u64 t, %1; cvt.u32.u64 %0, t; }" : "=r"(a) : "l"(p));
    return a;
}
__device__ __forceinline__ float bf_round(float x) {
    return __bfloat162float(__float2bfloat16(x));
}
__device__ __forceinline__ uint32_t pack_bf16x2(float hi, float lo) {
    uint32_t r;
    asm("cvt.rn.bf16x2.f32 %0, %1, %2;" : "=r"(r) : "f"(hi), "f"(lo));
    return r;
}
__device__ __forceinline__ void ldsm4(uint32_t* r, uint32_t addr) {
    asm volatile("ldmatrix.sync.aligned.m8n8.x4.shared.b16 {%0,%1,%2,%3}, [%4];"
                 : "=r"(r[0]), "=r"(r[1]), "=r"(r[2]), "=r"(r[3]) : "r"(addr));
}
__device__ __forceinline__ void mma16816(float* c, const uint32_t* a, uint32_t b0, uint32_t b1) {
    asm volatile("mma.sync.aligned.m16n8k16.row.col.f32.bf16.bf16.f32 "
                 "{%0,%1,%2,%3}, {%4,%5,%6,%7}, {%8,%9}, {%0,%1,%2,%3};"
                 : "+f"(c[0]), "+f"(c[1]), "+f"(c[2]), "+f"(c[3])
                 : "r"(a[0]), "r"(a[1]), "r"(a[2]), "r"(a[3]), "r"(b0), "r"(b1));
}
#define CP16(smaddr, gptr) \
    asm volatile("cp.async.cg.shared.global [%0], [%1], 16;" :: "r"(smaddr), "l"(gptr))
#define CP_COMMIT() asm volatile("cp.async.commit_group;" ::: "memory")
#define CP_WAIT0()  asm volatile("cp.async.wait_group 0;" ::: "memory")

// ============================ weight prep ==================================
__global__ void prep_weights(const float* __restrict__ Wv, const float* __restrict__ Wso,
                             const float* __restrict__ Waw, const float* __restrict__ Wo,
                             const float* __restrict__ bso, const float* __restrict__ baw)
{
    int idx = blockIdx.x * 256 + threadIdx.x;
    if (idx < 256 * 256) {
        int n = idx >> 8, k = idx & 255;
        float v = Wv[k * 256 + n];
        float h = bf_round(v);
        g_WvT_hi[n * 256 + k] = __float2bfloat16(h);
        g_WvT_lo[n * 256 + k] = __float2bfloat16(v - h);
        float o = Wo[k * 256 + n];
        float ho = bf_round(o);
        g_WoT_hi[n * 256 + k] = __float2bfloat16(ho);
        g_WoT_lo[n * 256 + k] = __float2bfloat16(o - ho);
    }
    if (idx < 256 * 512) {
        int n = idx >> 9, k = idx & 511;
        float v = 0.f;
        if (n < 128)      v = Wso[k * 128 + n];
        else if (n < 192) v = Waw[k * 64 + (n - 128)];
        float h = bf_round(v);
        g_W2T_hi[n * 512 + k] = __float2bfloat16(h);
        g_W2T_lo[n * 512 + k] = __float2bfloat16(v - h);
    }
    if (idx < 256) {
        float b = 0.f;
        if (idx < 128)      b = bso[idx];
        else if (idx < 192) b = baw[idx - 128];
        g_bias2[idx] = b;
    }
}

// ============================ mma.sync GEMM v4 =============================
// A fp32 (converted to bf16 hi/lo in-kernel), B pre-split bf16 via cp.async.
// 512 threads, 16 warps (4x4), warp tile 32x32, k-chunk 32, 2-stage.
// ~32 accumulator regs/thread -> no register cap needed, 4 warps/SMSP.
#define ROWB   80
#define T_AHI  0
#define T_ALO  10240
#define T_BHI  20480
#define T_BLO  30720
#define STAGEB 40960
#define SMEM_DYN_BYTES (2 * STAGEB)

template <int MODE>
__global__ __launch_bounds__(512, 1)
void tsa_gemm(const float* __restrict__ A, const float* __restrict__ Aq,
              const float* __restrict__ bias, const float* __restrict__ resid,
              float* __restrict__ outp)
{
    constexpr int KT   = (MODE == 1) ? 512 : 256;
    constexpr int MTOT = (MODE == 0) ? 80000 : 40000;
    constexpr int NC   = KT / 32;

    extern __shared__ char sm[];
    const uint32_t smb = smem_u32(sm);

    const int tid  = threadIdx.x;
    const int lane = tid & 31;
    const int wid  = tid >> 5;       // 0..15
    const int wm   = wid >> 2;       // 0..3 (32 rows)
    const int wn   = wid & 3;        // 0..3 (32 cols)
    const int m0   = blockIdx.x * 128;
    const int n0   = blockIdx.y * 128;

    const float* Abase = (MODE == 2) ? g_attn : A;
    const __nv_bfloat16* BTh = (MODE == 0) ? g_WvT_hi : (MODE == 1) ? g_W2T_hi : g_WoT_hi;
    const __nv_bfloat16* BTl = (MODE == 0) ? g_WvT_lo : (MODE == 1) ? g_W2T_lo : g_WoT_lo;

    // per-thread staging: row = tid>>2 (0..127), k-sub = (tid&3)*8
    const int arow = tid >> 2;
    const int seg  = tid & 3;           // B: 16B seg; A: 8-float block
    const int akb  = seg * 8;
    int agrow = m0 + arow; if (agrow > MTOT - 1) agrow = MTOT - 1;
    const int bn = n0 + arow;

    const int grp = lane >> 3, r = lane & 7;
    const uint32_t a_off = (uint32_t)((wm * 32 + ((grp & 1) << 3) + r) * ROWB + (grp >> 1) * 16);
    const uint32_t b_off = (uint32_t)((wn * 32 + ((grp >> 1) << 3) + r) * ROWB + (grp & 1) * 16);

    float acc[2][4][4];
    #pragma unroll
    for (int mt = 0; mt < 2; mt++)
        #pragma unroll
        for (int nt = 0; nt < 4; nt++)
            #pragma unroll
            for (int i = 0; i < 4; i++) acc[mt][nt][i] = 0.f;

    float av[8];

    // ---- B stage via cp.async (one 16B op per tile per thread) ----
    auto stage_B = [&](int k0, int s) {
        const __nv_bfloat16* pbh = BTh + (size_t)bn * KT + k0 + seg * 8;
        const __nv_bfloat16* pbl = BTl + (size_t)bn * KT + k0 + seg * 8;
        uint32_t d = smb + s * STAGEB + arow * ROWB + seg * 16;
        CP16(d + T_BHI, pbh);
        CP16(d + T_BLO, pbl);
        CP_COMMIT();
    };
    // ---- A fp32 load into regs ----
    auto load_A = [&](int k0) {
        const float* src = Abase; int kl = k0;
        if (MODE == 1 && k0 >= 256) { src = Aq; kl = k0 - 256; }
        const float4* p = (const float4*)(src + (size_t)agrow * 256 + kl + akb);
        float4 v0 = p[0], v1 = p[1];
        av[0] = v0.x; av[1] = v0.y; av[2] = v0.z; av[3] = v0.w;
        av[4] = v1.x; av[5] = v1.y; av[6] = v1.z; av[7] = v1.w;
    };
    // ---- convert av -> bf16 hi/lo, STS into stage s ----
    auto store_A = [&](int s) {
        uint32_t hp[4], lp[4];
        #pragma unroll
        for (int j = 0; j < 4; j++) {
            float x0 = av[2*j], x1 = av[2*j+1];
            float h0 = bf_round(x0), h1 = bf_round(x1);
            hp[j] = pack_bf16x2(h1, h0);
            lp[j] = pack_bf16x2(x1 - h1, x0 - h0);
        }
        char* dst = sm + s * STAGEB + arow * ROWB + akb * 2;
        *(uint4*)(dst + T_AHI) = *(uint4*)hp;
        *(uint4*)(dst + T_ALO) = *(uint4*)lp;
    };

    // ---- prologue: chunk 0 into stage 0 ----
    stage_B(0, 0);
    load_A(0);
    store_A(0);
    CP_WAIT0();
    __syncthreads();

    for (int c = 0; c < NC; c++) {
        const int stg  = c & 1;
        const int nstg = stg ^ 1;
        const bool more = (c + 1 < NC);

        if (more) {
            stage_B((c + 1) * 32, nstg);
            load_A((c + 1) * 32);
        }

        const uint32_t base = smb + stg * STAGEB;
        #pragma unroll
        for (int ks = 0; ks < 32; ks += 16) {
            uint32_t ah[2][4], al[2][4];
            #pragma unroll
            for (int mt = 0; mt < 2; mt++) {
                ldsm4(ah[mt], base + T_AHI + a_off + mt * (16 * ROWB) + ks * 2);
                ldsm4(al[mt], base + T_ALO + a_off + mt * (16 * ROWB) + ks * 2);
            }
            #pragma unroll
            for (int pr = 0; pr < 2; pr++) {
                uint32_t bh[4], bl[4];
                ldsm4(bh, base + T_BHI + b_off + pr * (16 * ROWB) + ks * 2);
                ldsm4(bl, base + T_BLO + b_off + pr * (16 * ROWB) + ks * 2);
                #pragma unroll
                for (int mt = 0; mt < 2; mt++)
                    #pragma unroll
                    for (int n2 = 0; n2 < 2; n2++) {
                        float* a = acc[mt][pr * 2 + n2];
                        mma16816(a, ah[mt], bh[n2 * 2], bh[n2 * 2 + 1]);
                        mma16816(a, ah[mt], bl[n2 * 2], bl[n2 * 2 + 1]);
                        mma16816(a, al[mt], bh[n2 * 2], bh[n2 * 2 + 1]);
                    }
            }
        }

        if (more) {
            store_A(nstg);
            CP_WAIT0();
            __syncthreads();
        }
    }

    // ---- epilogue ----
    #pragma unroll
    for (int mt = 0; mt < 2; mt++) {
        const int rbase = m0 + wm * 32 + mt * 16 + (lane >> 2);
        #pragma unroll
        for (int nt = 0; nt < 4; nt++) {
            const int gn = n0 + wn * 32 + nt * 8 + (lane & 3) * 2;
            #pragma unroll
            for (int hf = 0; hf < 2; hf++) {
                const int row = rbase + hf * 8;
                if (row >= MTOT) continue;
                float c0 = acc[mt][nt][hf * 2], c1 = acc[mt][nt][hf * 2 + 1];
                if (MODE == 0) {
                    __half2 o = __floats2half2_rn(c0 + bias[gn], c1 + bias[gn + 1]);
                    *(__half2*)&g_value[(size_t)row * 256 + gn] = o;
                } else if (MODE == 1) {
                    if (gn >= 192) continue;
                    float2 o = make_float2(c0 + g_bias2[gn], c1 + g_bias2[gn + 1]);
                    if (gn < 128) *(float2*)&g_so[(size_t)row * 128 + gn] = o;
                    else          *(float2*)&g_aw[(size_t)row * 64 + (gn - 128)] = o;
                } else {
                    float2 q = *(const float2*)&resid[(size_t)row * 256 + gn];
                    float2 o = make_float2(c0 + bias[gn] + q.x, c1 + bias[gn + 1] + q.y);
                    *(float2*)&outp[(size_t)row * 256 + gn] = o;
                }
            }
        }
    }
}

// ============================ sampling (round-6 v3) ========================
__global__ __launch_bounds__(256)
void sample_kernel(const float* __restrict__ ref2d)
{
    const int gw = blockIdx.x * 8 + (threadIdx.x >> 5);
    const int q  = gw >> 1;
    const int lane = threadIdx.x & 31;
    const int h  = ((gw & 1) << 2) + (lane >> 3);
    const int c4 = (lane & 7) << 2;

    const float* __restrict__ so_q = &g_so[(size_t)q * 128];
    const float* __restrict__ aw_q = &g_aw[(size_t)q * 64];

    float4 acc = make_float4(0.f, 0.f, 0.f, 0.f);

    #pragma unroll
    for (int b = 0; b < NBQc; b++) {
        const int awbase = (h * 2 + b) * 4;
        float a0 = aw_q[awbase + 0], a1 = aw_q[awbase + 1];
        float a2 = aw_q[awbase + 2], a3 = aw_q[awbase + 3];
        float mx = fmaxf(fmaxf(a0, a1), fmaxf(a2, a3));
        float e0 = __expf(a0 - mx), e1 = __expf(a1 - mx);
        float e2 = __expf(a2 - mx), e3 = __expf(a3 - mx);
        float inv = 1.f / (e0 + e1 + e2 + e3);
        float wts[4] = {e0 * inv, e1 * inv, e2 * inv, e3 * inv};

        const float rx = ref2d[((size_t)b * NQc + q) * 2 + 0];
        const float ry = ref2d[((size_t)b * NQc + q) * 2 + 1];
        const __half* __restrict__ vbase =
            g_value + (size_t)b * (NQc * EDc) + (h << 5) + c4;

        uint32_t offs[4][4];
        float    w[4][4];
        #pragma unroll
        for (int p = 0; p < NPc; p++) {
            const int j = (awbase + p) * 2;
            float x = fmaf(so_q[j + 0], 1.0f, rx * (float)Wc) - 0.5f;
            float y = fmaf(so_q[j + 1], 1.0f, ry * (float)Hc) - 0.5f;
            float x0f = floorf(x), y0f = floorf(y);
            float wx = x - x0f, wy = y - y0f;
            int ix0 = (int)x0f, iy0 = (int)y0f;

            float mx0 = ((unsigned)ix0       < (unsigned)Wc) ? 1.f : 0.f;
            float mx1 = ((unsigned)(ix0 + 1) < (unsigned)Wc) ? 1.f : 0.f;
            float my0 = ((unsigned)iy0       < (unsigned)Hc) ? 1.f : 0.f;
            float my1 = ((unsigned)(iy0 + 1) < (unsigned)Hc) ? 1.f : 0.f;

            float wt = wts[p];
            w[p][0] = (1.f - wx) * (1.f - wy) * mx0 * my0 * wt;
            w[p][1] = wx * (1.f - wy) * mx1 * my0 * wt;
            w[p][2] = (1.f - wx) * wy * mx0 * my1 * wt;
            w[p][3] = wx * wy * mx1 * my1 * wt;

            int ix0c = min(max(ix0, 0), Wc - 1);
            int ix1c = min(max(ix0 + 1, 0), Wc - 1);
            int iy0c = min(max(iy0, 0), Hc - 1);
            int iy1c = min(max(iy0 + 1, 0), Hc - 1);

            uint32_t r0 = (uint32_t)(iy0c * Wc) << 8;
            uint32_t r1 = (uint32_t)(iy1c * Wc) << 8;
            uint32_t cx0 = (uint32_t)ix0c << 8;
            uint32_t cx1 = (uint32_t)ix1c << 8;
            offs[p][0] = r0 + cx0;
            offs[p][1] = r0 + cx1;
            offs[p][2] = r1 + cx0;
            offs[p][3] = r1 + cx1;
        }

        uint2 d[4][4];
        #pragma unroll
        for (int p = 0; p < NPc; p++)
            #pragma unroll
            for (int c = 0; c < 4; c++)
                d[p][c] = *(const uint2*)(vbase + offs[p][c]);

        #pragma unroll
        for (int p = 0; p < NPc; p++) {
            #pragma unroll
            for (int c = 0; c < 4; c++) {
                float2 lo = __half22float2(*(const __half2*)&d[p][c].x);
                float2 hi = __half22float2(*(const __half2*)&d[p][c].y);
                float ww = w[p][c];
                acc.x = fmaf(ww, lo.x, acc.x);
                acc.y = fmaf(ww, lo.y, acc.y);
                acc.z = fmaf(ww, hi.x, acc.z);
                acc.w = fmaf(ww, hi.y, acc.w);
            }
        }
    }
    float4 o = make_float4(0.5f * acc.x, 0.5f * acc.y, 0.5f * acc.z, 0.5f * acc.w);
    *(float4*)&g_attn[(size_t)q * EDc + (h << 5) + c4] = o;
}

// ============================================================================
extern "C" void kernel_launch(void* const* d_in, const int* in_sizes, int n_in,
                              void* d_out, int out_size)
{
    const float* query    = (const float*)d_in[0];
    const float* prev_bev = (const float*)d_in[1];
    const float* ref2d    = (const float*)d_in[3];
    const float* Wv       = (const float*)d_in[4];
    const float* bv       = (const float*)d_in[5];
    const float* Wso      = (const float*)d_in[6];
    const float* bso      = (const float*)d_in[7];
    const float* Waw      = (const float*)d_in[8];
    const float* baw      = (const float*)d_in[9];
    const float* Wo       = (const float*)d_in[10];
    const float* bo       = (const float*)d_in[11];
    float* out = (float*)d_out;

    cudaFuncSetAttribute(tsa_gemm<0>, cudaFuncAttributeMaxDynamicSharedMemorySize, SMEM_DYN_BYTES);
    cudaFuncSetAttribute(tsa_gemm<1>, cudaFuncAttributeMaxDynamicSharedMemorySize, SMEM_DYN_BYTES);
    cudaFuncSetAttribute(tsa_gemm<2>, cudaFuncAttributeMaxDynamicSharedMemorySize, SMEM_DYN_BYTES);

    prep_weights<<<512, 256>>>(Wv, Wso, Waw, Wo, bso, baw);

    // 1) value projection: 80000 x 256 x 256 (fp16 output)
    tsa_gemm<0><<<dim3(625, 2), 512, SMEM_DYN_BYTES>>>(prev_bev, nullptr, bv, nullptr, nullptr);

    // 2) offsets + logits: 40000 x 512 x 192
    tsa_gemm<1><<<dim3(313, 2), 512, SMEM_DYN_BYTES>>>(prev_bev, query, nullptr, nullptr, nullptr);

    // 3) softmax + bilinear sampling (fp16 gathers) -> g_attn fp32
    sample_kernel<<<NQc * 2 / 8, 256>>>(ref2d);

    // 4) output projection + residual: 40000 x 256 x 256
    tsa_gemm<2><<<dim3(313, 2), 512, SMEM_DYN_BYTES>>>(g_attn, nullptr, bo, query, out);
}

// round 14
// speedup vs baseline: 3.5678x; 1.2781x over previous
#include <cuda_runtime.h>
#include <cuda_bf16.h>
#include <cuda_fp16.h>
#include <cstdint>
#include <math.h>

#define NQc   40000
#define EDc   256
#define NHc   8
#define NBQc  2
#define NPc   4
#define Hc    200
#define Wc    200

// ---------------- scratch (device globals) ---------------------------------
// NOTE: total static footprint must stay well under ~128 MiB (device-globals
// arena growth trips the harness allocation guard — rounds 9/11).
__device__ __half g_value[NBQc * NQc * EDc];  // 41.0 MB fp16
__device__ float g_so[NQc * 128];             // 20.5 MB
__device__ float g_aw[NQc * 64];              // 10.2 MB
__device__ float g_attn[NQc * EDc];           // 41.0 MB

// pre-transposed fp16 weights: [N][K] row-major (~0.5 MB)
__device__ __half g_WvT[256 * 256];
__device__ __half g_WoT[256 * 256];
__device__ __half g_W2T[256 * 512];   // n<128: Wso, 128..191: Waw, >=192: 0
__device__ float g_bias2[256];

// ============================ helpers ======================================
__device__ __forceinline__ uint32_t smem_u32(const void* p) {
    uint32_t a;
    asm("{ .reg .u64 t; cvta.to.shared.u64 t, %1; cvt.u32.u64 %0, t; }" : "=r"(a) : "l"(p));
    return a;
}
__device__ __forceinline__ void ldsm4(uint32_t* r, uint32_t addr) {
    asm volatile("ldmatrix.sync.aligned.m8n8.x4.shared.b16 {%0,%1,%2,%3}, [%4];"
                 : "=r"(r[0]), "=r"(r[1]), "=r"(r[2]), "=r"(r[3]) : "r"(addr));
}
__device__ __forceinline__ void mma16816(float* c, const uint32_t* a, uint32_t b0, uint32_t b1) {
    asm volatile("mma.sync.aligned.m16n8k16.row.col.f32.f16.f16.f32 "
                 "{%0,%1,%2,%3}, {%4,%5,%6,%7}, {%8,%9}, {%0,%1,%2,%3};"
                 : "+f"(c[0]), "+f"(c[1]), "+f"(c[2]), "+f"(c[3])
                 : "r"(a[0]), "r"(a[1]), "r"(a[2]), "r"(a[3]), "r"(b0), "r"(b1));
}
#define CP16(smaddr, gptr) \
    asm volatile("cp.async.cg.shared.global [%0], [%1], 16;" :: "r"(smaddr), "l"(gptr))
#define CP_COMMIT() asm volatile("cp.async.commit_group;" ::: "memory")
#define CP_WAIT0()  asm volatile("cp.async.wait_group 0;" ::: "memory")

// ============================ weight prep ==================================
__global__ void prep_weights(const float* __restrict__ Wv, const float* __restrict__ Wso,
                             const float* __restrict__ Waw, const float* __restrict__ Wo,
                             const float* __restrict__ bso, const float* __restrict__ baw)
{
    int idx = blockIdx.x * 256 + threadIdx.x;
    if (idx < 256 * 256) {
        int n = idx >> 8, k = idx & 255;
        g_WvT[n * 256 + k] = __float2half(Wv[k * 256 + n]);
        g_WoT[n * 256 + k] = __float2half(Wo[k * 256 + n]);
    }
    if (idx < 256 * 512) {
        int n = idx >> 9, k = idx & 511;
        float v = 0.f;
        if (n < 128)      v = Wso[k * 128 + n];
        else if (n < 192) v = Waw[k * 64 + (n - 128)];
        g_W2T[n * 512 + k] = __float2half(v);
    }
    if (idx < 256) {
        float b = 0.f;
        if (idx < 128)      b = bso[idx];
        else if (idx < 192) b = baw[idx - 128];
        g_bias2[idx] = b;
    }
}

// ============================ mma.sync GEMM v5 (fp16) ======================
// A fp32 (converted to fp16 in-kernel), B pre-transposed fp16 via cp.async.
// Single-pass fp16 MMA with fp32 accumulate: exact products, only input
// quantization error (2^-11). 512 threads, 16 warps (4x4), warp tile 32x32,
// k-chunk 32, 2-stage.
#define ROWB   80
#define T_A    0
#define T_B    10240
#define STAGEB 20480
#define SMEM_DYN_BYTES (2 * STAGEB)

template <int MODE>
__global__ __launch_bounds__(512, 1)
void tsa_gemm(const float* __restrict__ A, const float* __restrict__ Aq,
              const float* __restrict__ bias, const float* __restrict__ resid,
              float* __restrict__ outp)
{
    constexpr int KT   = (MODE == 1) ? 512 : 256;
    constexpr int MTOT = (MODE == 0) ? 80000 : 40000;
    constexpr int NC   = KT / 32;

    extern __shared__ char sm[];
    const uint32_t smb = smem_u32(sm);

    const int tid  = threadIdx.x;
    const int lane = tid & 31;
    const int wid  = tid >> 5;       // 0..15
    const int wm   = wid >> 2;       // 0..3 (32 rows)
    const int wn   = wid & 3;        // 0..3 (32 cols)
    const int m0   = blockIdx.x * 128;
    const int n0   = blockIdx.y * 128;

    const float* Abase = (MODE == 2) ? g_attn : A;
    const __half* BT = (MODE == 0) ? g_WvT : (MODE == 1) ? g_W2T : g_WoT;

    // per-thread staging: row = tid>>2 (0..127), k-sub = (tid&3)*8
    const int arow = tid >> 2;
    const int seg  = tid & 3;
    const int akb  = seg * 8;
    int agrow = m0 + arow; if (agrow > MTOT - 1) agrow = MTOT - 1;
    const int bn = n0 + arow;

    const int grp = lane >> 3, r = lane & 7;
    const uint32_t a_off = (uint32_t)((wm * 32 + ((grp & 1) << 3) + r) * ROWB + (grp >> 1) * 16);
    const uint32_t b_off = (uint32_t)((wn * 32 + ((grp >> 1) << 3) + r) * ROWB + (grp & 1) * 16);

    float acc[2][4][4];
    #pragma unroll
    for (int mt = 0; mt < 2; mt++)
        #pragma unroll
        for (int nt = 0; nt < 4; nt++)
            #pragma unroll
            for (int i = 0; i < 4; i++) acc[mt][nt][i] = 0.f;

    float av[8];

    // ---- B stage via cp.async (one 16B op per thread) ----
    auto stage_B = [&](int k0, int s) {
        const __half* pb = BT + (size_t)bn * KT + k0 + seg * 8;
        uint32_t d = smb + s * STAGEB + T_B + arow * ROWB + seg * 16;
        CP16(d, pb);
        CP_COMMIT();
    };
    // ---- A fp32 load into regs ----
    auto load_A = [&](int k0) {
        const float* src = Abase; int kl = k0;
        if (MODE == 1 && k0 >= 256) { src = Aq; kl = k0 - 256; }
        const float4* p = (const float4*)(src + (size_t)agrow * 256 + kl + akb);
        float4 v0 = p[0], v1 = p[1];
        av[0] = v0.x; av[1] = v0.y; av[2] = v0.z; av[3] = v0.w;
        av[4] = v1.x; av[5] = v1.y; av[6] = v1.z; av[7] = v1.w;
    };
    // ---- convert av -> fp16, STS into stage s ----
    auto store_A = [&](int s) {
        uint32_t hp[4];
        #pragma unroll
        for (int j = 0; j < 4; j++) {
            __half2 h = __floats2half2_rn(av[2*j], av[2*j+1]);
            hp[j] = *(uint32_t*)&h;
        }
        char* dst = sm + s * STAGEB + T_A + arow * ROWB + akb * 2;
        *(uint4*)dst = *(uint4*)hp;
    };

    // ---- prologue: chunk 0 into stage 0 ----
    stage_B(0, 0);
    load_A(0);
    store_A(0);
    CP_WAIT0();
    __syncthreads();

    for (int c = 0; c < NC; c++) {
        const int stg  = c & 1;
        const int nstg = stg ^ 1;
        const bool more = (c + 1 < NC);

        if (more) {
            stage_B((c + 1) * 32, nstg);
            load_A((c + 1) * 32);
        }

        const uint32_t base = smb + stg * STAGEB;
        #pragma unroll
        for (int ks = 0; ks < 32; ks += 16) {
            uint32_t ah[2][4];
            #pragma unroll
            for (int mt = 0; mt < 2; mt++)
                ldsm4(ah[mt], base + T_A + a_off + mt * (16 * ROWB) + ks * 2);
            #pragma unroll
            for (int pr = 0; pr < 2; pr++) {
                uint32_t bh[4];
                ldsm4(bh, base + T_B + b_off + pr * (16 * ROWB) + ks * 2);
                #pragma unroll
                for (int mt = 0; mt < 2; mt++)
                    #pragma unroll
                    for (int n2 = 0; n2 < 2; n2++)
                        mma16816(acc[mt][pr * 2 + n2], ah[mt], bh[n2 * 2], bh[n2 * 2 + 1]);
            }
        }

        if (more) {
            store_A(nstg);
            CP_WAIT0();
            __syncthreads();
        }
    }

    // ---- epilogue ----
    #pragma unroll
    for (int mt = 0; mt < 2; mt++) {
        const int rbase = m0 + wm * 32 + mt * 16 + (lane >> 2);
        #pragma unroll
        for (int nt = 0; nt < 4; nt++) {
            const int gn = n0 + wn * 32 + nt * 8 + (lane & 3) * 2;
            #pragma unroll
            for (int hf = 0; hf < 2; hf++) {
                const int row = rbase + hf * 8;
                if (row >= MTOT) continue;
                float c0 = acc[mt][nt][hf * 2], c1 = acc[mt][nt][hf * 2 + 1];
                if (MODE == 0) {
                    __half2 o = __floats2half2_rn(c0 + bias[gn], c1 + bias[gn + 1]);
                    *(__half2*)&g_value[(size_t)row * 256 + gn] = o;
                } else if (MODE == 1) {
                    if (gn >= 192) continue;
                    float2 o = make_float2(c0 + g_bias2[gn], c1 + g_bias2[gn + 1]);
                    if (gn < 128) *(float2*)&g_so[(size_t)row * 128 + gn] = o;
                    else          *(float2*)&g_aw[(size_t)row * 64 + (gn - 128)] = o;
                } else {
                    float2 q = *(const float2*)&resid[(size_t)row * 256 + gn];
                    float2 o = make_float2(c0 + bias[gn] + q.x, c1 + bias[gn + 1] + q.y);
                    *(float2*)&outp[(size_t)row * 256 + gn] = o;
                }
            }
        }
    }
}

// ============================ sampling (round-6 v3, unchanged) =============
__global__ __launch_bounds__(256)
void sample_kernel(const float* __restrict__ ref2d)
{
    const int gw = blockIdx.x * 8 + (threadIdx.x >> 5);
    const int q  = gw >> 1;
    const int lane = threadIdx.x & 31;
    const int h  = ((gw & 1) << 2) + (lane >> 3);
    const int c4 = (lane & 7) << 2;

    const float* __restrict__ so_q = &g_so[(size_t)q * 128];
    const float* __restrict__ aw_q = &g_aw[(size_t)q * 64];

    float4 acc = make_float4(0.f, 0.f, 0.f, 0.f);

    #pragma unroll
    for (int b = 0; b < NBQc; b++) {
        const int awbase = (h * 2 + b) * 4;
        float a0 = aw_q[awbase + 0], a1 = aw_q[awbase + 1];
        float a2 = aw_q[awbase + 2], a3 = aw_q[awbase + 3];
        float mx = fmaxf(fmaxf(a0, a1), fmaxf(a2, a3));
        float e0 = __expf(a0 - mx), e1 = __expf(a1 - mx);
        float e2 = __expf(a2 - mx), e3 = __expf(a3 - mx);
        float inv = 1.f / (e0 + e1 + e2 + e3);
        float wts[4] = {e0 * inv, e1 * inv, e2 * inv, e3 * inv};

        const float rx = ref2d[((size_t)b * NQc + q) * 2 + 0];
        const float ry = ref2d[((size_t)b * NQc + q) * 2 + 1];
        const __half* __restrict__ vbase =
            g_value + (size_t)b * (NQc * EDc) + (h << 5) + c4;

        uint32_t offs[4][4];
        float    w[4][4];
        #pragma unroll
        for (int p = 0; p < NPc; p++) {
            const int j = (awbase + p) * 2;
            float x = fmaf(so_q[j + 0], 1.0f, rx * (float)Wc) - 0.5f;
            float y = fmaf(so_q[j + 1], 1.0f, ry * (float)Hc) - 0.5f;
            float x0f = floorf(x), y0f = floorf(y);
            float wx = x - x0f, wy = y - y0f;
            int ix0 = (int)x0f, iy0 = (int)y0f;

            float mx0 = ((unsigned)ix0       < (unsigned)Wc) ? 1.f : 0.f;
            float mx1 = ((unsigned)(ix0 + 1) < (unsigned)Wc) ? 1.f : 0.f;
            float my0 = ((unsigned)iy0       < (unsigned)Hc) ? 1.f : 0.f;
            float my1 = ((unsigned)(iy0 + 1) < (unsigned)Hc) ? 1.f : 0.f;

            float wt = wts[p];
            w[p][0] = (1.f - wx) * (1.f - wy) * mx0 * my0 * wt;
            w[p][1] = wx * (1.f - wy) * mx1 * my0 * wt;
            w[p][2] = (1.f - wx) * wy * mx0 * my1 * wt;
            w[p][3] = wx * wy * mx1 * my1 * wt;

            int ix0c = min(max(ix0, 0), Wc - 1);
            int ix1c = min(max(ix0 + 1, 0), Wc - 1);
            int iy0c = min(max(iy0, 0), Hc - 1);
            int iy1c = min(max(iy0 + 1, 0), Hc - 1);

            uint32_t r0 = (uint32_t)(iy0c * Wc) << 8;
            uint32_t r1 = (uint32_t)(iy1c * Wc) << 8;
            uint32_t cx0 = (uint32_t)ix0c << 8;
            uint32_t cx1 = (uint32_t)ix1c << 8;
            offs[p][0] = r0 + cx0;
            offs[p][1] = r0 + cx1;
            offs[p][2] = r1 + cx0;
            offs[p][3] = r1 + cx1;
        }

        uint2 d[4][4];
        #pragma unroll
        for (int p = 0; p < NPc; p++)
            #pragma unroll
            for (int c = 0; c < 4; c++)
                d[p][c] = *(const uint2*)(vbase + offs[p][c]);

        #pragma unroll
        for (int p = 0; p < NPc; p++) {
            #pragma unroll
            for (int c = 0; c < 4; c++) {
                float2 lo = __half22float2(*(const __half2*)&d[p][c].x);
                float2 hi = __half22float2(*(const __half2*)&d[p][c].y);
                float ww = w[p][c];
                acc.x = fmaf(ww, lo.x, acc.x);
                acc.y = fmaf(ww, lo.y, acc.y);
                acc.z = fmaf(ww, hi.x, acc.z);
                acc.w = fmaf(ww, hi.y, acc.w);
            }
        }
    }
    float4 o = make_float4(0.5f * acc.x, 0.5f * acc.y, 0.5f * acc.z, 0.5f * acc.w);
    *(float4*)&g_attn[(size_t)q * EDc + (h << 5) + c4] = o;
}

// ============================================================================
extern "C" void kernel_launch(void* const* d_in, const int* in_sizes, int n_in,
                              void* d_out, int out_size)
{
    const float* query    = (const float*)d_in[0];
    const float* prev_bev = (const float*)d_in[1];
    const float* ref2d    = (const float*)d_in[3];
    const float* Wv       = (const float*)d_in[4];
    const float* bv       = (const float*)d_in[5];
    const float* Wso      = (const float*)d_in[6];
    const float* bso      = (const float*)d_in[7];
    const float* Waw      = (const float*)d_in[8];
    const float* baw      = (const float*)d_in[9];
    const float* Wo       = (const float*)d_in[10];
    const float* bo       = (const float*)d_in[11];
    float* out = (float*)d_out;

    cudaFuncSetAttribute(tsa_gemm<0>, cudaFuncAttributeMaxDynamicSharedMemorySize, SMEM_DYN_BYTES);
    cudaFuncSetAttribute(tsa_gemm<1>, cudaFuncAttributeMaxDynamicSharedMemorySize, SMEM_DYN_BYTES);
    cudaFuncSetAttribute(tsa_gemm<2>, cudaFuncAttributeMaxDynamicSharedMemorySize, SMEM_DYN_BYTES);

    prep_weights<<<512, 256>>>(Wv, Wso, Waw, Wo, bso, baw);

    // 1) value projection: 80000 x 256 x 256 (fp16 output)
    tsa_gemm<0><<<dim3(625, 2), 512, SMEM_DYN_BYTES>>>(prev_bev, nullptr, bv, nullptr, nullptr);

    // 2) offsets + logits: 40000 x 512 x 192
    tsa_gemm<1><<<dim3(313, 2), 512, SMEM_DYN_BYTES>>>(prev_bev, query, nullptr, nullptr, nullptr);

    // 3) softmax + bilinear sampling (fp16 gathers) -> g_attn fp32
    sample_kernel<<<NQc * 2 / 8, 256>>>(ref2d);

    // 4) output projection + residual: 40000 x 256 x 256
    tsa_gemm<2><<<dim3(313, 2), 512, SMEM_DYN_BYTES>>>(g_attn, nullptr, bo, query, out);
}